// round 11
// baseline (speedup 1.0000x reference)
#include <cuda_runtime.h>
#include <cuda_fp16.h>
#include <cstdint>

#define N_NODES 20000
#define N_EDGES 320000

// ---------------- scratch (device globals; no allocation allowed) ----------
__device__ __half g_xl16[N_NODES * 1024];  // fp16 per-head features (gather source)
__device__ float  g_h1[N_NODES * 1024];    // layer1 residual GEMM output (read once)
__device__ float  g_h2[N_NODES * 256];     // layer2 residual GEMM output (read once)
__device__ __half g_fc1h[N_NODES * 256];   // fp16 fc1 output
__device__ float  g_fc2[N_NODES * 256];
__device__ __half g_at[N_NODES * 1024];    // fp16 A operand (x, then h1, then h2)
__device__ __half g_wt[2048 * 1024];       // fp16 transposed packed weights [N,K]
__device__ float  g_asrc[N_NODES * 4];
__device__ float  g_adst[N_NODES * 4];
__device__ int    g_deg[N_NODES];
__device__ int    g_off[N_NODES + 1];
__device__ int    g_cur[N_NODES];
__device__ int    g_esrc[N_EDGES];         // src node of each edge, grouped by dst

// ---------------- helpers ---------------------------------------------------
__device__ __forceinline__ void mma_f16(float* d, const unsigned* a, const unsigned* b) {
    asm volatile(
        "mma.sync.aligned.m16n8k16.row.col.f32.f16.f16.f32 "
        "{%0,%1,%2,%3}, {%4,%5,%6,%7}, {%8,%9}, {%0,%1,%2,%3};"
        : "+f"(d[0]), "+f"(d[1]), "+f"(d[2]), "+f"(d[3])
        : "r"(a[0]), "r"(a[1]), "r"(a[2]), "r"(a[3]), "r"(b[0]), "r"(b[1]));
}

__device__ __forceinline__ void ldsm4(unsigned& r0, unsigned& r1, unsigned& r2, unsigned& r3,
                                      uint32_t addr) {
    asm volatile("ldmatrix.sync.aligned.m8n8.x4.shared.b16 {%0,%1,%2,%3}, [%4];"
                 : "=r"(r0), "=r"(r1), "=r"(r2), "=r"(r3) : "r"(addr));
}

__device__ __forceinline__ void cp16(void* smem, const void* gmem, bool pred) {
    unsigned sa = (unsigned)__cvta_generic_to_shared(smem);
    int sz = pred ? 16 : 0;
    asm volatile("cp.async.cg.shared.global [%0], [%1], 16, %2;"
                 :: "r"(sa), "l"(gmem), "r"(sz));
}

// ---------------- fp16 conversion passes -------------------------------------
__global__ void cvt_fp16_kernel(const float* __restrict__ in, __half* __restrict__ out, int n) {
    int i = (blockIdx.x * blockDim.x + threadIdx.x) * 8;
    if (i >= n) return;
    float4 v0 = *(const float4*)(in + i);
    float4 v1 = *(const float4*)(in + i + 4);
    __half2 h[4];
    h[0] = __floats2half2_rn(v0.x, v0.y);
    h[1] = __floats2half2_rn(v0.z, v0.w);
    h[2] = __floats2half2_rn(v1.x, v1.y);
    h[3] = __floats2half2_rn(v1.z, v1.w);
    *(uint4*)(out + i) = *(uint4*)h;
}

// weights: W[K,N] fp32 -> out[N,K] fp16 (transposed). K,N multiples of 32.
__global__ void cvt_fp16_transpose_kernel(const float* __restrict__ in, __half* __restrict__ out,
                                          int K, int N) {
    __shared__ float t[32][33];
    int k0 = blockIdx.y * 32, n0 = blockIdx.x * 32;
    int tx = threadIdx.x, ty = threadIdx.y;  // 32 x 8
    #pragma unroll
    for (int j = 0; j < 32; j += 8)
        t[ty + j][tx] = in[(size_t)(k0 + ty + j) * N + n0 + tx];
    __syncthreads();
    #pragma unroll
    for (int j = 0; j < 32; j += 8)
        out[(size_t)(n0 + ty + j) * K + k0 + tx] = __float2half_rn(t[tx][ty + j]);
}

// ---------------- CSR build ---------------------------------------------------
__global__ void zero_deg_kernel(int* __restrict__ deg) {
    int i = blockIdx.x * blockDim.x + threadIdx.x;
    if (i < N_NODES) deg[i] = 0;
}

__global__ void hist_kernel(const int* __restrict__ dst, int* __restrict__ deg) {
    int e = blockIdx.x * blockDim.x + threadIdx.x;
    if (e < N_EDGES) atomicAdd(&deg[dst[e]], 1);
}

__global__ __launch_bounds__(256) void scan_kernel(
    const int* __restrict__ deg, int* __restrict__ off, int* __restrict__ cur)
{
    __shared__ int partial[256];
    const int tid = threadIdx.x;
    const int CH = (N_NODES + 255) / 256;
    const int base = tid * CH;

    int s = 0;
    for (int j = 0; j < CH; j++) {
        int i = base + j;
        if (i < N_NODES) s += deg[i];
    }
    partial[tid] = s;
    __syncthreads();
    for (int o = 1; o < 256; o <<= 1) {
        int v = (tid >= o) ? partial[tid - o] : 0;
        __syncthreads();
        partial[tid] += v;
        __syncthreads();
    }
    int run = partial[tid] - s;
    for (int j = 0; j < CH; j++) {
        int i = base + j;
        if (i < N_NODES) {
            off[i] = run;
            cur[i] = run;
            run += deg[i];
        }
    }
    if (tid == 255) off[N_NODES] = run;
}

__global__ void scatter_kernel(const int* __restrict__ src, const int* __restrict__ dst,
                               int* __restrict__ cur, int* __restrict__ esrc) {
    int e = blockIdx.x * blockDim.x + threadIdx.x;
    if (e >= N_EDGES) return;
    int pos = atomicAdd(&cur[dst[e]], 1);
    esrc[pos] = src[e];
}

// ---------------- fp16 tensor-core GEMM, cp.async 3-stage, 64-half k-tiles ---
// C_all[M,N] = A[M,K] @ Bt[N,K]^T. Split output: columns [0,Nsplit) go fp32 to
// C (row stride Nsplit, bias biasA); columns [Nsplit,N) go fp16 to C16 (row
// stride N-Nsplit, bias biasB). Nsplit % 128 == 0 so each CTA is in one region.
// CTA tile 128x128, K-tile 64 halves (144B row pitch, ldmatrix conflict-free),
// 8 warps (2x4) 64x32, mma m16n8k16, single sync per k-tile.
// Requires N % 128 == 0, K % 64 == 0; M guarded.
#define GBM 128
#define GBN 128
#define HK 64
#define ROWW 36                  // words per smem row (64 halves + 8 pad = 144B)
#define TSZW (128 * ROWW)        // words per (A or B) tile = 4608
#define STAGES 3
#define GEMM_SMEM (STAGES * 2 * TSZW * 4)   // 110592 bytes

template <int ACT>  // 0: none, 1: leaky_relu(0.01)
__global__ __launch_bounds__(256, 2) void mma_gemm_kernel(
    const __half* __restrict__ A, const __half* __restrict__ Bt,
    const float* __restrict__ biasA, const float* __restrict__ biasB,
    float* __restrict__ C, __half* __restrict__ C16,
    int M, int N, int K, int Nsplit)
{
    extern __shared__ unsigned smem[];
    unsigned* As = smem;
    unsigned* Bs = smem + STAGES * TSZW;

    const int tid = threadIdx.x;
    const int warp = tid >> 5, lane = tid & 31;
    const int g = lane >> 2, tg = lane & 3;
    const int wr = (warp >> 2) * 64;
    const int wc = (warp & 3) * 32;

    const int bm = blockIdx.y, bn = blockIdx.x;

    // staging: thread covers (row = tid>>1, halves cH..cH+31) = half a row
    const int rowS = tid >> 1;
    const int cH = (tid & 1) * 32;
    const int rowA = bm * GBM + rowS;
    const bool avalid = rowA < M;
    const __half* Ap = avalid ? (A + (size_t)rowA * K + cH) : A;
    const __half* Bp = Bt + (size_t)(bn * GBN + rowS) * K + cH;
    const int sOff = rowS * ROWW + (tid & 1) * 16;   // words

    // ldmatrix per-lane byte offsets within a tile (144B row pitch)
    const uint32_t sbase = (uint32_t)__cvta_generic_to_shared(smem);
    const uint32_t aLds = (uint32_t)(wr + (lane & 15)) * 144u + ((lane >> 4) & 1) * 16u;
    const uint32_t bLds = (uint32_t)(wc + ((lane >> 4) & 1) * 8 + (lane & 7)) * 144u
                        + ((lane >> 3) & 1) * 16u;

    const int KT = K / HK;

    float acc[4][4][4];
    #pragma unroll
    for (int mt = 0; mt < 4; mt++)
        #pragma unroll
        for (int nt = 0; nt < 4; nt++)
            #pragma unroll
            for (int i = 0; i < 4; i++) acc[mt][nt][i] = 0.0f;

    // prologue: stage tiles 0..STAGES-2
    #pragma unroll
    for (int kt = 0; kt < STAGES - 1; kt++) {
        if (kt < KT) {
            unsigned* as = As + (kt % STAGES) * TSZW;
            unsigned* bs = Bs + (kt % STAGES) * TSZW;
            const __half* ap = Ap + (avalid ? kt * HK : 0);
            const __half* bp = Bp + kt * HK;
            #pragma unroll
            for (int j = 0; j < 4; j++) {
                cp16(&as[sOff + j * 4], ap + j * 8, avalid);
                cp16(&bs[sOff + j * 4], bp + j * 8, true);
            }
        }
        asm volatile("cp.async.commit_group;");
    }

    for (int kt = 0; kt < KT; kt++) {
        // tile kt resident
        asm volatile("cp.async.wait_group %0;" :: "n"(STAGES - 2));
        // single barrier: also proves all warps finished reading buffer
        // (kt-1)%STAGES == (kt+STAGES-1)%STAGES before we overwrite it below
        __syncthreads();

        int kf = kt + STAGES - 1;
        if (kf < KT) {
            unsigned* as = As + (kf % STAGES) * TSZW;
            unsigned* bs = Bs + (kf % STAGES) * TSZW;
            const __half* ap = Ap + (avalid ? kf * HK : 0);
            const __half* bp = Bp + kf * HK;
            #pragma unroll
            for (int j = 0; j < 4; j++) {
                cp16(&as[sOff + j * 4], ap + j * 8, avalid);
                cp16(&bs[sOff + j * 4], bp + j * 8, true);
            }
        }
        asm volatile("cp.async.commit_group;");

        const uint32_t aBase = sbase + (uint32_t)((kt % STAGES) * TSZW) * 4u + aLds;
        const uint32_t bBase = sbase + (uint32_t)((STAGES + (kt % STAGES)) * TSZW) * 4u + bLds;

        #pragma unroll
        for (int kk = 0; kk < 4; kk++) {
            unsigned af[4][4];
            unsigned bf[4][2];
            #pragma unroll
            for (int mt = 0; mt < 4; mt++)
                ldsm4(af[mt][0], af[mt][1], af[mt][2], af[mt][3],
                      aBase + mt * 2304u + kk * 32u);
            #pragma unroll
            for (int p = 0; p < 2; p++)
                ldsm4(bf[p * 2][0], bf[p * 2][1], bf[p * 2 + 1][0], bf[p * 2 + 1][1],
                      bBase + p * 2304u + kk * 32u);
            #pragma unroll
            for (int mt = 0; mt < 4; mt++)
                #pragma unroll
                for (int nt = 0; nt < 4; nt++)
                    mma_f16(acc[mt][nt], af[mt], bf[nt]);
        }
    }

    // epilogue: whole CTA tile lies in one output region
    const int colBase = bn * GBN;
    const bool rA = colBase < Nsplit;
    const int Wd = rA ? Nsplit : (N - Nsplit);
    const int cb = (rA ? colBase : colBase - Nsplit) + wc;
    const float* bias = rA ? biasA : biasB;

    float bv[4][2];
    #pragma unroll
    for (int nt = 0; nt < 4; nt++) {
        int col = cb + nt * 8 + 2 * tg;
        bv[nt][0] = bias ? bias[col] : 0.0f;
        bv[nt][1] = bias ? bias[col + 1] : 0.0f;
    }

    #pragma unroll
    for (int mt = 0; mt < 4; mt++) {
        #pragma unroll
        for (int i = 0; i < 2; i++) {
            int row = bm * GBM + wr + mt * 16 + g + i * 8;
            if (row >= M) continue;
            size_t rb = (size_t)row * Wd + cb;
            #pragma unroll
            for (int nt = 0; nt < 4; nt++) {
                float2 v;
                v.x = acc[mt][nt][i * 2 + 0] + bv[nt][0];
                v.y = acc[mt][nt][i * 2 + 1] + bv[nt][1];
                if (ACT == 1) {
                    v.x = v.x > 0.f ? v.x : 0.01f * v.x;
                    v.y = v.y > 0.f ? v.y : 0.01f * v.y;
                }
                if (rA) *(float2*)(C + rb + nt * 8 + 2 * tg) = v;
                else    *(__half2*)(C16 + rb + nt * 8 + 2 * tg) = __floats2half2_rn(v.x, v.y);
            }
        }
    }
}

// ---------------- attention scores (fp16 xl) ---------------------------------
__global__ __launch_bounds__(256) void attn_scores_kernel(
    const __half* __restrict__ xl,
    const float* __restrict__ att_src, const float* __restrict__ att_dst,
    float* __restrict__ asrc, float* __restrict__ adst)
{
    int task = blockIdx.x * 8 + (threadIdx.x >> 5);
    if (task >= N_NODES * 4) return;
    int lane = threadIdx.x & 31;
    int n = task >> 2, h = task & 3;

    const __half* xp = xl + (size_t)n * 1024 + h * 256 + lane * 8;
    const float* sp = att_src + h * 256 + lane * 8;
    const float* dp = att_dst + h * 256 + lane * 8;

    uint4 raw = *(const uint4*)xp;
    __half2* hh = (__half2*)&raw;
    float2 p0 = __half22float2(hh[0]);
    float2 p1 = __half22float2(hh[1]);
    float2 p2 = __half22float2(hh[2]);
    float2 p3 = __half22float2(hh[3]);
    float4 a0 = *(const float4*)(sp), a1 = *(const float4*)(sp + 4);
    float4 b0 = *(const float4*)(dp), b1 = *(const float4*)(dp + 4);

    float s1 = p0.x*a0.x + p0.y*a0.y + p1.x*a0.z + p1.y*a0.w
             + p2.x*a1.x + p2.y*a1.y + p3.x*a1.z + p3.y*a1.w;
    float s2 = p0.x*b0.x + p0.y*b0.y + p1.x*b0.z + p1.y*b0.w
             + p2.x*b1.x + p2.y*b1.y + p3.x*b1.z + p3.y*b1.w;

    #pragma unroll
    for (int off = 16; off > 0; off >>= 1) {
        s1 += __shfl_xor_sync(0xffffffffu, s1, off);
        s2 += __shfl_xor_sync(0xffffffffu, s2, off);
    }
    if (lane == 0) {
        asrc[task] = s1;
        adst[task] = s2;
    }
}

// ---------------- layer1 aggregation: fp16 gather, fp16 'at' output ----------
__global__ __launch_bounds__(256) void gat_aggregate1_kernel(
    const int* __restrict__ off, const int* __restrict__ esrc,
    const __half* __restrict__ xl, const float* __restrict__ asrc,
    const float* __restrict__ adst, const float* __restrict__ h1,
    __half* __restrict__ out_at)
{
    int task = blockIdx.x * 8 + (threadIdx.x >> 5);
    if (task >= N_NODES * 4) return;
    int lane = threadIdx.x & 31;
    int n = task >> 2, h = task & 3;

    const float ad = adst[n * 4 + h];
    const int j0 = off[n], j1 = off[n + 1];

    float u[8] = {0.f, 0.f, 0.f, 0.f, 0.f, 0.f, 0.f, 0.f};
    float ssum = 0.f;

    for (int j = j0; j < j1; j++) {
        int s = esrc[j];
        float a = asrc[s * 4 + h] + ad;
        a = a > 0.f ? a : 0.2f * a;
        float w = __expf(a);
        ssum += w;
        uint4 raw = *(const uint4*)(xl + (size_t)s * 1024 + h * 256 + lane * 8);
        __half2* hh = (__half2*)&raw;
        float2 p0 = __half22float2(hh[0]);
        float2 p1 = __half22float2(hh[1]);
        float2 p2 = __half22float2(hh[2]);
        float2 p3 = __half22float2(hh[3]);
        u[0] += w * p0.x; u[1] += w * p0.y; u[2] += w * p1.x; u[3] += w * p1.y;
        u[4] += w * p2.x; u[5] += w * p2.y; u[6] += w * p3.x; u[7] += w * p3.y;
    }

    float inv = 1.0f / (ssum + 1e-16f);
    size_t base = (size_t)n * 1024 + h * 256 + lane * 8;
    float4 r0 = *(const float4*)(h1 + base);
    float4 r1 = *(const float4*)(h1 + base + 4);
    __half2 o[4];
    o[0] = __floats2half2_rn(r0.x + u[0] * inv, r0.y + u[1] * inv);
    o[1] = __floats2half2_rn(r0.z + u[2] * inv, r0.w + u[3] * inv);
    o[2] = __floats2half2_rn(r1.x + u[4] * inv, r1.y + u[5] * inv);
    o[3] = __floats2half2_rn(r1.z + u[6] * inv, r1.w + u[7] * inv);
    *(uint4*)(out_at + base) = *(uint4*)o;
}

// ---------------- layer2 aggregation: head-mean, fp16 gather/out -------------
__global__ __launch_bounds__(256) void gat_aggregate2_kernel(
    const int* __restrict__ off, const int* __restrict__ esrc,
    const __half* __restrict__ xl, const float* __restrict__ asrc,
    const float* __restrict__ adst, const float* __restrict__ h2,
    __half* __restrict__ out_at)
{
    int n = blockIdx.x * 8 + (threadIdx.x >> 5);
    if (n >= N_NODES) return;
    int lane = threadIdx.x & 31;

    float4 ad = *(const float4*)(adst + n * 4);
    const int j0 = off[n], j1 = off[n + 1];

    float u[4][8];
    #pragma unroll
    for (int h = 0; h < 4; h++)
        #pragma unroll
        for (int q = 0; q < 8; q++) u[h][q] = 0.f;
    float4 ssum = make_float4(0.f, 0.f, 0.f, 0.f);

    for (int j = j0; j < j1; j++) {
        int s = esrc[j];
        float4 as = *(const float4*)(asrc + s * 4);
        float4 e;
        e.x = as.x + ad.x; e.x = e.x > 0.f ? e.x : 0.2f * e.x;
        e.y = as.y + ad.y; e.y = e.y > 0.f ? e.y : 0.2f * e.y;
        e.z = as.z + ad.z; e.z = e.z > 0.f ? e.z : 0.2f * e.z;
        e.w = as.w + ad.w; e.w = e.w > 0.f ? e.w : 0.2f * e.w;
        float w[4];
        w[0] = __expf(e.x); w[1] = __expf(e.y); w[2] = __expf(e.z); w[3] = __expf(e.w);
        ssum.x += w[0]; ssum.y += w[1]; ssum.z += w[2]; ssum.w += w[3];

        const __half* sp = xl + (size_t)s * 1024 + lane * 8;
        #pragma unroll
        for (int h = 0; h < 4; h++) {
            uint4 raw = *(const uint4*)(sp + h * 256);
            __half2* hh = (__half2*)&raw;
            float2 p0 = __half22float2(hh[0]);
            float2 p1 = __half22float2(hh[1]);
            float2 p2 = __half22float2(hh[2]);
            float2 p3 = __half22float2(hh[3]);
            u[h][0] += w[h] * p0.x; u[h][1] += w[h] * p0.y;
            u[h][2] += w[h] * p1.x; u[h][3] += w[h] * p1.y;
            u[h][4] += w[h] * p2.x; u[h][5] += w[h] * p2.y;
            u[h][6] += w[h] * p3.x; u[h][7] += w[h] * p3.y;
        }
    }

    float i0 = 0.25f / (ssum.x + 1e-16f);
    float i1 = 0.25f / (ssum.y + 1e-16f);
    float i2 = 0.25f / (ssum.z + 1e-16f);
    float i3 = 0.25f / (ssum.w + 1e-16f);

    size_t base = (size_t)n * 256 + lane * 8;
    float4 r0 = *(const float4*)(h2 + base);
    float4 r1 = *(const float4*)(h2 + base + 4);
    float o[8];
    o[0] = r0.x + i0*u[0][0] + i1*u[1][0] + i2*u[2][0] + i3*u[3][0];
    o[1] = r0.y + i0*u[0][1] + i1*u[1][1] + i2*u[2][1] + i3*u[3][1];
    o[2] = r0.z + i0*u[0][2] + i1*u[1][2] + i2*u[2][2] + i3*u[3][2];
    o[3] = r0.w + i0*u[0][3] + i1*u[1][3] + i2*u[2][3] + i3*u[3][3];
    o[4] = r1.x + i0*u[0][4] + i1*u[1][4] + i2*u[2][4] + i3*u[3][4];
    o[5] = r1.y + i0*u[0][5] + i1*u[1][5] + i2*u[2][5] + i3*u[3][5];
    o[6] = r1.z + i0*u[0][6] + i1*u[1][6] + i2*u[2][6] + i3*u[3][6];
    o[7] = r1.w + i0*u[0][7] + i1*u[1][7] + i2*u[2][7] + i3*u[3][7];
    __half2 ho[4];
    ho[0] = __floats2half2_rn(o[0], o[1]);
    ho[1] = __floats2half2_rn(o[2], o[3]);
    ho[2] = __floats2half2_rn(o[4], o[5]);
    ho[3] = __floats2half2_rn(o[6], o[7]);
    *(uint4*)(out_at + base) = *(uint4*)ho;
}

// ---------------- output heads ----------------------------------------------
__global__ __launch_bounds__(256) void heads_kernel(
    const float* __restrict__ fc,
    const float* __restrict__ Wb, const float* __restrict__ bb,
    const float* __restrict__ Ws, const float* __restrict__ bs,
    float* __restrict__ out)
{
    int n = blockIdx.x * 8 + (threadIdx.x >> 5);
    if (n >= N_NODES) return;
    int lane = threadIdx.x & 31;

    float acc[7] = {0.f, 0.f, 0.f, 0.f, 0.f, 0.f, 0.f};
    #pragma unroll
    for (int i = 0; i < 8; i++) {
        int k = i * 32 + lane;
        float v = fc[(size_t)n * 256 + k];
        acc[0] += v * Wb[k * 2 + 0];
        acc[1] += v * Wb[k * 2 + 1];
        #pragma unroll
        for (int j = 0; j < 5; j++) acc[2 + j] += v * Ws[k * 5 + j];
    }
    #pragma unroll
    for (int off = 16; off > 0; off >>= 1) {
        #pragma unroll
        for (int j = 0; j < 7; j++) acc[j] += __shfl_xor_sync(0xffffffffu, acc[j], off);
    }
    if (lane == 0) {
        out[(size_t)n * 2 + 0] = acc[0] + bb[0];
        out[(size_t)n * 2 + 1] = acc[1] + bb[1];
        float* sev = out + (size_t)N_NODES * 2 + (size_t)n * 5;
        #pragma unroll
        for (int j = 0; j < 5; j++) sev[j] = acc[2 + j] + bs[j];
    }
}

// ---------------- launch ------------------------------------------------------
static inline void cvt(const float* in, __half* out, int n) {
    cvt_fp16_kernel<<<(n / 8 + 255) / 256, 256>>>(in, out, n);
}
static inline void cvtT(const float* W, __half* out, int K, int N) {
    dim3 grid(N / 32, K / 32);
    cvt_fp16_transpose_kernel<<<grid, dim3(32, 8)>>>(W, out, K, N);
}

extern "C" void kernel_launch(void* const* d_in, const int* in_sizes, int n_in,
                              void* d_out, int out_size)
{
    const float* x        = (const float*)d_in[0];
    const int*   ei       = (const int*)d_in[1];
    const float* W1       = (const float*)d_in[2];
    const float* att_src1 = (const float*)d_in[3];
    const float* att_dst1 = (const float*)d_in[4];
    const float* Wres1    = (const float*)d_in[5];
    const float* b1       = (const float*)d_in[6];
    const float* W2       = (const float*)d_in[7];
    const float* att_src2 = (const float*)d_in[8];
    const float* att_dst2 = (const float*)d_in[9];
    const float* Wres2    = (const float*)d_in[10];
    const float* b2       = (const float*)d_in[11];
    const float* Wfc      = (const float*)d_in[12];
    const float* bfc      = (const float*)d_in[13];
    const float* Wb       = (const float*)d_in[14];
    const float* bb       = (const float*)d_in[15];
    const float* Ws       = (const float*)d_in[16];
    const float* bs       = (const float*)d_in[17];
    float* out = (float*)d_out;

    const int* src = ei;
    const int* dst = ei + N_EDGES;

    float *h1, *h2, *fc2, *asrc, *adst;
    __half *xl16, *at, *wt, *fc1h;
    int *deg, *off, *cur, *esrc;
    cudaGetSymbolAddress((void**)&xl16, g_xl16);
    cudaGetSymbolAddress((void**)&h1,   g_h1);
    cudaGetSymbolAddress((void**)&h2,   g_h2);
    cudaGetSymbolAddress((void**)&fc1h, g_fc1h);
    cudaGetSymbolAddress((void**)&fc2,  g_fc2);
    cudaGetSymbolAddress((void**)&at,   g_at);
    cudaGetSymbolAddress((void**)&wt,   g_wt);
    cudaGetSymbolAddress((void**)&asrc, g_asrc);
    cudaGetSymbolAddress((void**)&adst, g_adst);
    cudaGetSymbolAddress((void**)&deg,  g_deg);
    cudaGetSymbolAddress((void**)&off,  g_off);
    cudaGetSymbolAddress((void**)&cur,  g_cur);
    cudaGetSymbolAddress((void**)&esrc, g_esrc);

    static bool attr_done = false;
    if (!attr_done) {
        cudaFuncSetAttribute(mma_gemm_kernel<0>,
                             cudaFuncAttributeMaxDynamicSharedMemorySize, GEMM_SMEM);
        cudaFuncSetAttribute(mma_gemm_kernel<1>,
                             cudaFuncAttributeMaxDynamicSharedMemorySize, GEMM_SMEM);
        attr_done = true;
    }

    const int mRows = (N_NODES + GBM - 1) / GBM;
    const int attnBlocks = (N_NODES * 4 + 7) / 8;
    const int nodeBlocks = (N_NODES + 7) / 8;
    const int edgeBlocks = (N_EDGES + 255) / 256;

    // launches 1-3: operand prep (packed weights: [Wres1^T ; W1^T] = [2048, 768])
    cvt(x, at, N_NODES * 768);
    cvtT(Wres1, wt, 768, 1024);
    cvtT(W1, wt + (size_t)1024 * 768, 768, 1024);

    // launch 4 (ncu window): fused layer1 GEMM, N=2048
    //   cols [0,1024)    -> h1 (fp32) + b1
    //   cols [1024,2048) -> xl16 (fp16)
    {
        dim3 grid(2048 / GBN, mRows);
        mma_gemm_kernel<0><<<grid, 256, GEMM_SMEM>>>(at, wt, b1, nullptr, h1, xl16,
                                                     N_NODES, 2048, 768, 1024);
    }

    // CSR build
    zero_deg_kernel<<<(N_NODES + 255) / 256, 256>>>(deg);
    hist_kernel<<<edgeBlocks, 256>>>(dst, deg);
    scan_kernel<<<1, 256>>>(deg, off, cur);
    scatter_kernel<<<edgeBlocks, 256>>>(src, dst, cur, esrc);

    // ===== layer 1 aggregation -> fp16 'at' =====
    attn_scores_kernel<<<attnBlocks, 256>>>(xl16, att_src1, att_dst1, asrc, adst);
    gat_aggregate1_kernel<<<attnBlocks, 256>>>(off, esrc, xl16, asrc, adst, h1, at);

    // ===== fused layer2 GEMM, N=1280: cols [0,256)->h2+b2, [256,1280)->xl16 ===
    cvtT(Wres2, wt, 1024, 256);
    cvtT(W2, wt + (size_t)256 * 1024, 1024, 1024);
    {
        dim3 grid(1280 / GBN, mRows);
        mma_gemm_kernel<0><<<grid, 256, GEMM_SMEM>>>(at, wt, b2, nullptr, h2, xl16,
                                                     N_NODES, 1280, 1024, 256);
    }
    attn_scores_kernel<<<attnBlocks, 256>>>(xl16, att_src2, att_dst2, asrc, adst);
    gat_aggregate2_kernel<<<nodeBlocks, 256>>>(off, esrc, xl16, asrc, adst, h2, at);

    // ===== shared FC twice =====
    cvtT(Wfc, wt, 256, 256);
    {
        dim3 grid(256 / GBN, mRows);
        // fc1: all columns fp16 out with bias+leaky (region B, Nsplit=0)
        mma_gemm_kernel<1><<<grid, 256, GEMM_SMEM>>>(at, wt, nullptr, bfc, nullptr, fc1h,
                                                     N_NODES, 256, 256, 0);
        // fc2: all columns fp32 out with bias (region A, Nsplit=256)
        mma_gemm_kernel<0><<<grid, 256, GEMM_SMEM>>>(fc1h, wt, bfc, nullptr, fc2, nullptr,
                                                     N_NODES, 256, 256, 256);
    }

    // ===== heads =====
    heads_kernel<<<nodeBlocks, 256>>>(fc2, Wb, bb, Ws, bs, out);
}

// round 12
// speedup vs baseline: 1.0894x; 1.0894x over previous
#include <cuda_runtime.h>
#include <cuda_fp16.h>
#include <cstdint>

#define N_NODES 20000
#define N_EDGES 320000

// ---------------- scratch (device globals; no allocation allowed) ----------
__device__ __half g_xl16[N_NODES * 1024];  // fp16 per-head features (gather source)
__device__ float  g_h1[N_NODES * 1024];    // layer1 residual GEMM output (read once)
__device__ float  g_h2[N_NODES * 256];     // layer2 residual GEMM output (read once)
__device__ __half g_fc1h[N_NODES * 256];   // fp16 fc1 output
__device__ float  g_fc2[N_NODES * 256];
__device__ __half g_at[N_NODES * 1024];    // fp16 A operand (x, then h1, then h2)
__device__ __half g_wt[2048 * 1024];       // fp16 transposed packed weights [N,K]
__device__ float  g_asrc[N_NODES * 4];
__device__ float  g_adst[N_NODES * 4];
__device__ int    g_deg[N_NODES];
__device__ int    g_off[N_NODES + 1];
__device__ int    g_cur[N_NODES];
__device__ int    g_esrc[N_EDGES];         // src node of each edge, grouped by dst

// ---------------- helpers ---------------------------------------------------
__device__ __forceinline__ void mma_f16(float* d, const unsigned* a, const unsigned* b) {
    asm volatile(
        "mma.sync.aligned.m16n8k16.row.col.f32.f16.f16.f32 "
        "{%0,%1,%2,%3}, {%4,%5,%6,%7}, {%8,%9}, {%0,%1,%2,%3};"
        : "+f"(d[0]), "+f"(d[1]), "+f"(d[2]), "+f"(d[3])
        : "r"(a[0]), "r"(a[1]), "r"(a[2]), "r"(a[3]), "r"(b[0]), "r"(b[1]));
}

__device__ __forceinline__ void ldsm4(unsigned& r0, unsigned& r1, unsigned& r2, unsigned& r3,
                                      uint32_t addr) {
    asm volatile("ldmatrix.sync.aligned.m8n8.x4.shared.b16 {%0,%1,%2,%3}, [%4];"
                 : "=r"(r0), "=r"(r1), "=r"(r2), "=r"(r3) : "r"(addr));
}

__device__ __forceinline__ void cp16(void* smem, const void* gmem, bool pred) {
    unsigned sa = (unsigned)__cvta_generic_to_shared(smem);
    int sz = pred ? 16 : 0;
    asm volatile("cp.async.cg.shared.global [%0], [%1], 16, %2;"
                 :: "r"(sa), "l"(gmem), "r"(sz));
}

// ---------------- fp16 conversion passes -------------------------------------
__global__ void cvt_fp16_kernel(const float* __restrict__ in, __half* __restrict__ out, int n) {
    int i = (blockIdx.x * blockDim.x + threadIdx.x) * 8;
    if (i >= n) return;
    float4 v0 = *(const float4*)(in + i);
    float4 v1 = *(const float4*)(in + i + 4);
    __half2 h[4];
    h[0] = __floats2half2_rn(v0.x, v0.y);
    h[1] = __floats2half2_rn(v0.z, v0.w);
    h[2] = __floats2half2_rn(v1.x, v1.y);
    h[3] = __floats2half2_rn(v1.z, v1.w);
    *(uint4*)(out + i) = *(uint4*)h;
}

// weights: W[K,N] fp32 -> out[N,K] fp16 (transposed). K,N multiples of 32.
__global__ void cvt_fp16_transpose_kernel(const float* __restrict__ in, __half* __restrict__ out,
                                          int K, int N) {
    __shared__ float t[32][33];
    int k0 = blockIdx.y * 32, n0 = blockIdx.x * 32;
    int tx = threadIdx.x, ty = threadIdx.y;  // 32 x 8
    #pragma unroll
    for (int j = 0; j < 32; j += 8)
        t[ty + j][tx] = in[(size_t)(k0 + ty + j) * N + n0 + tx];
    __syncthreads();
    #pragma unroll
    for (int j = 0; j < 32; j += 8)
        out[(size_t)(n0 + ty + j) * K + k0 + tx] = __float2half_rn(t[tx][ty + j]);
}

// ---------------- CSR build ---------------------------------------------------
__global__ void zero_deg_kernel(int* __restrict__ deg) {
    int i = blockIdx.x * blockDim.x + threadIdx.x;
    if (i < N_NODES) deg[i] = 0;
}

__global__ void hist_kernel(const int* __restrict__ dst, int* __restrict__ deg) {
    int e = blockIdx.x * blockDim.x + threadIdx.x;
    if (e < N_EDGES) atomicAdd(&deg[dst[e]], 1);
}

__global__ __launch_bounds__(256) void scan_kernel(
    const int* __restrict__ deg, int* __restrict__ off, int* __restrict__ cur)
{
    __shared__ int partial[256];
    const int tid = threadIdx.x;
    const int CH = (N_NODES + 255) / 256;
    const int base = tid * CH;

    int s = 0;
    for (int j = 0; j < CH; j++) {
        int i = base + j;
        if (i < N_NODES) s += deg[i];
    }
    partial[tid] = s;
    __syncthreads();
    for (int o = 1; o < 256; o <<= 1) {
        int v = (tid >= o) ? partial[tid - o] : 0;
        __syncthreads();
        partial[tid] += v;
        __syncthreads();
    }
    int run = partial[tid] - s;
    for (int j = 0; j < CH; j++) {
        int i = base + j;
        if (i < N_NODES) {
            off[i] = run;
            cur[i] = run;
            run += deg[i];
        }
    }
    if (tid == 255) off[N_NODES] = run;
}

__global__ void scatter_kernel(const int* __restrict__ src, const int* __restrict__ dst,
                               int* __restrict__ cur, int* __restrict__ esrc) {
    int e = blockIdx.x * blockDim.x + threadIdx.x;
    if (e >= N_EDGES) return;
    int pos = atomicAdd(&cur[dst[e]], 1);
    esrc[pos] = src[e];
}

// ---------------- fp16 tensor-core GEMM, cp.async 5-stage, single-sync -------
// C_all[M,N] = A[M,K] @ Bt[N,K]^T. Split output: columns [0,Nsplit) go fp32 to
// C (row stride Nsplit, bias biasA); columns [Nsplit,N) go fp16 to C16 (row
// stride N-Nsplit, bias biasB). Nsplit % 128 == 0 so each CTA is in one region.
// CTA tile 128x128, K-tile 32 halves (80B row pitch, ldmatrix conflict-free),
// 8 warps (2x4) 64x32, mma m16n8k16, single sync per k-tile.
// Requires N % 128 == 0, K % 32 == 0; M guarded.
#define GBM 128
#define GBN 128
#define HK 32
#define ROWW 20
#define TSZW (128 * ROWW)
#define STAGES 5
#define GEMM_SMEM (STAGES * 2 * TSZW * 4)   // 102400 bytes

template <int ACT>  // 0: none, 1: leaky_relu(0.01)
__global__ __launch_bounds__(256, 2) void mma_gemm_kernel(
    const __half* __restrict__ A, const __half* __restrict__ Bt,
    const float* __restrict__ biasA, const float* __restrict__ biasB,
    float* __restrict__ C, __half* __restrict__ C16,
    int M, int N, int K, int Nsplit)
{
    extern __shared__ unsigned smem[];
    unsigned* As = smem;
    unsigned* Bs = smem + STAGES * TSZW;

    const int tid = threadIdx.x;
    const int warp = tid >> 5, lane = tid & 31;
    const int g = lane >> 2, tg = lane & 3;
    const int wr = (warp >> 2) * 64;
    const int wc = (warp & 3) * 32;

    const int bm = blockIdx.y, bn = blockIdx.x;

    const int rowS = tid >> 1;
    const int rowA = bm * GBM + rowS;
    const bool avalid = rowA < M;
    const __half* Ap = avalid ? (A + (size_t)rowA * K + (tid & 1) * 16) : A;
    const __half* Bp = Bt + (size_t)(bn * GBN + rowS) * K + (tid & 1) * 16;
    const int sOff = rowS * ROWW + (tid & 1) * 8;

    // ldmatrix per-lane byte offsets within a tile (80B row pitch)
    const uint32_t sbase = (uint32_t)__cvta_generic_to_shared(smem);
    const uint32_t aLds = (uint32_t)(wr + (lane & 15)) * 80u + ((lane >> 4) & 1) * 16u;
    const uint32_t bLds = (uint32_t)(wc + ((lane >> 4) & 1) * 8 + (lane & 7)) * 80u
                        + ((lane >> 3) & 1) * 16u;

    const int KT = K / HK;

    float acc[4][4][4];
    #pragma unroll
    for (int mt = 0; mt < 4; mt++)
        #pragma unroll
        for (int nt = 0; nt < 4; nt++)
            #pragma unroll
            for (int i = 0; i < 4; i++) acc[mt][nt][i] = 0.0f;

    // prologue: stage tiles 0..STAGES-2
    #pragma unroll
    for (int kt = 0; kt < STAGES - 1; kt++) {
        if (kt < KT) {
            unsigned* as = As + (kt % STAGES) * TSZW;
            unsigned* bs = Bs + (kt % STAGES) * TSZW;
            const __half* ap = Ap + (avalid ? kt * HK : 0);
            const __half* bp = Bp + kt * HK;
            cp16(&as[sOff],     ap,     avalid);
            cp16(&as[sOff + 4], ap + 8, avalid);
            cp16(&bs[sOff],     bp,     true);
            cp16(&bs[sOff + 4], bp + 8, true);
        }
        asm volatile("cp.async.commit_group;");
    }

    for (int kt = 0; kt < KT; kt++) {
        // tile kt resident
        asm volatile("cp.async.wait_group %0;" :: "n"(STAGES - 2));
        // single barrier: also proves all warps finished reading buffer
        // (kt-1)%STAGES == (kt+STAGES-1)%STAGES before we overwrite it below
        __syncthreads();

        int kf = kt + STAGES - 1;
        if (kf < KT) {
            unsigned* as = As + (kf % STAGES) * TSZW;
            unsigned* bs = Bs + (kf % STAGES) * TSZW;
            const __half* ap = Ap + (avalid ? kf * HK : 0);
            const __half* bp = Bp + kf * HK;
            cp16(&as[sOff],     ap,     avalid);
            cp16(&as[sOff + 4], ap + 8, avalid);
            cp16(&bs[sOff],     bp,     true);
            cp16(&bs[sOff + 4], bp + 8, true);
        }
        asm volatile("cp.async.commit_group;");

        const uint32_t aBase = sbase + (uint32_t)((kt % STAGES) * TSZW) * 4u + aLds;
        const uint32_t bBase = sbase + (uint32_t)((STAGES + (kt % STAGES)) * TSZW) * 4u + bLds;

        #pragma unroll
        for (int kk = 0; kk < 2; kk++) {
            unsigned af[4][4];
            unsigned bf[4][2];
            #pragma unroll
            for (int mt = 0; mt < 4; mt++)
                ldsm4(af[mt][0], af[mt][1], af[mt][2], af[mt][3],
                      aBase + mt * 1280u + kk * 32u);
            #pragma unroll
            for (int p = 0; p < 2; p++)
                ldsm4(bf[p * 2][0], bf[p * 2][1], bf[p * 2 + 1][0], bf[p * 2 + 1][1],
                      bBase + p * 1280u + kk * 32u);
            #pragma unroll
            for (int mt = 0; mt < 4; mt++)
                #pragma unroll
                for (int nt = 0; nt < 4; nt++)
                    mma_f16(acc[mt][nt], af[mt], bf[nt]);
        }
    }

    // epilogue: whole CTA tile lies in one output region
    const int colBase = bn * GBN;
    const bool rA = colBase < Nsplit;
    const int Wd = rA ? Nsplit : (N - Nsplit);
    const int cb = (rA ? colBase : colBase - Nsplit) + wc;
    const float* bias = rA ? biasA : biasB;

    float bv[4][2];
    #pragma unroll
    for (int nt = 0; nt < 4; nt++) {
        int col = cb + nt * 8 + 2 * tg;
        bv[nt][0] = bias ? bias[col] : 0.0f;
        bv[nt][1] = bias ? bias[col + 1] : 0.0f;
    }

    #pragma unroll
    for (int mt = 0; mt < 4; mt++) {
        #pragma unroll
        for (int i = 0; i < 2; i++) {
            int row = bm * GBM + wr + mt * 16 + g + i * 8;
            if (row >= M) continue;
            size_t rb = (size_t)row * Wd + cb;
            #pragma unroll
            for (int nt = 0; nt < 4; nt++) {
                float2 v;
                v.x = acc[mt][nt][i * 2 + 0] + bv[nt][0];
                v.y = acc[mt][nt][i * 2 + 1] + bv[nt][1];
                if (ACT == 1) {
                    v.x = v.x > 0.f ? v.x : 0.01f * v.x;
                    v.y = v.y > 0.f ? v.y : 0.01f * v.y;
                }
                if (rA) *(float2*)(C + rb + nt * 8 + 2 * tg) = v;
                else    *(__half2*)(C16 + rb + nt * 8 + 2 * tg) = __floats2half2_rn(v.x, v.y);
            }
        }
    }
}

// ---------------- attention scores (fp16 xl) ---------------------------------
__global__ __launch_bounds__(256) void attn_scores_kernel(
    const __half* __restrict__ xl,
    const float* __restrict__ att_src, const float* __restrict__ att_dst,
    float* __restrict__ asrc, float* __restrict__ adst)
{
    int task = blockIdx.x * 8 + (threadIdx.x >> 5);
    if (task >= N_NODES * 4) return;
    int lane = threadIdx.x & 31;
    int n = task >> 2, h = task & 3;

    const __half* xp = xl + (size_t)n * 1024 + h * 256 + lane * 8;
    const float* sp = att_src + h * 256 + lane * 8;
    const float* dp = att_dst + h * 256 + lane * 8;

    uint4 raw = *(const uint4*)xp;
    __half2* hh = (__half2*)&raw;
    float2 p0 = __half22float2(hh[0]);
    float2 p1 = __half22float2(hh[1]);
    float2 p2 = __half22float2(hh[2]);
    float2 p3 = __half22float2(hh[3]);
    float4 a0 = *(const float4*)(sp), a1 = *(const float4*)(sp + 4);
    float4 b0 = *(const float4*)(dp), b1 = *(const float4*)(dp + 4);

    float s1 = p0.x*a0.x + p0.y*a0.y + p1.x*a0.z + p1.y*a0.w
             + p2.x*a1.x + p2.y*a1.y + p3.x*a1.z + p3.y*a1.w;
    float s2 = p0.x*b0.x + p0.y*b0.y + p1.x*b0.z + p1.y*b0.w
             + p2.x*b1.x + p2.y*b1.y + p3.x*b1.z + p3.y*b1.w;

    #pragma unroll
    for (int off = 16; off > 0; off >>= 1) {
        s1 += __shfl_xor_sync(0xffffffffu, s1, off);
        s2 += __shfl_xor_sync(0xffffffffu, s2, off);
    }
    if (lane == 0) {
        asrc[task] = s1;
        adst[task] = s2;
    }
}

// ---------------- layer1 aggregation: fp16 gather, fp16 'at' output ----------
__global__ __launch_bounds__(256) void gat_aggregate1_kernel(
    const int* __restrict__ off, const int* __restrict__ esrc,
    const __half* __restrict__ xl, const float* __restrict__ asrc,
    const float* __restrict__ adst, const float* __restrict__ h1,
    __half* __restrict__ out_at)
{
    int task = blockIdx.x * 8 + (threadIdx.x >> 5);
    if (task >= N_NODES * 4) return;
    int lane = threadIdx.x & 31;
    int n = task >> 2, h = task & 3;

    const float ad = adst[n * 4 + h];
    const int j0 = off[n], j1 = off[n + 1];

    float u[8] = {0.f, 0.f, 0.f, 0.f, 0.f, 0.f, 0.f, 0.f};
    float ssum = 0.f;

    for (int j = j0; j < j1; j++) {
        int s = esrc[j];
        float a = asrc[s * 4 + h] + ad;
        a = a > 0.f ? a : 0.2f * a;
        float w = __expf(a);
        ssum += w;
        uint4 raw = *(const uint4*)(xl + (size_t)s * 1024 + h * 256 + lane * 8);
        __half2* hh = (__half2*)&raw;
        float2 p0 = __half22float2(hh[0]);
        float2 p1 = __half22float2(hh[1]);
        float2 p2 = __half22float2(hh[2]);
        float2 p3 = __half22float2(hh[3]);
        u[0] += w * p0.x; u[1] += w * p0.y; u[2] += w * p1.x; u[3] += w * p1.y;
        u[4] += w * p2.x; u[5] += w * p2.y; u[6] += w * p3.x; u[7] += w * p3.y;
    }

    float inv = 1.0f / (ssum + 1e-16f);
    size_t base = (size_t)n * 1024 + h * 256 + lane * 8;
    float4 r0 = *(const float4*)(h1 + base);
    float4 r1 = *(const float4*)(h1 + base + 4);
    __half2 o[4];
    o[0] = __floats2half2_rn(r0.x + u[0] * inv, r0.y + u[1] * inv);
    o[1] = __floats2half2_rn(r0.z + u[2] * inv, r0.w + u[3] * inv);
    o[2] = __floats2half2_rn(r1.x + u[4] * inv, r1.y + u[5] * inv);
    o[3] = __floats2half2_rn(r1.z + u[6] * inv, r1.w + u[7] * inv);
    *(uint4*)(out_at + base) = *(uint4*)o;
}

// ---------------- layer2 aggregation: head-mean, fp16 gather/out -------------
__global__ __launch_bounds__(256) void gat_aggregate2_kernel(
    const int* __restrict__ off, const int* __restrict__ esrc,
    const __half* __restrict__ xl, const float* __restrict__ asrc,
    const float* __restrict__ adst, const float* __restrict__ h2,
    __half* __restrict__ out_at)
{
    int n = blockIdx.x * 8 + (threadIdx.x >> 5);
    if (n >= N_NODES) return;
    int lane = threadIdx.x & 31;

    float4 ad = *(const float4*)(adst + n * 4);
    const int j0 = off[n], j1 = off[n + 1];

    float u[4][8];
    #pragma unroll
    for (int h = 0; h < 4; h++)
        #pragma unroll
        for (int q = 0; q < 8; q++) u[h][q] = 0.f;
    float4 ssum = make_float4(0.f, 0.f, 0.f, 0.f);

    for (int j = j0; j < j1; j++) {
        int s = esrc[j];
        float4 as = *(const float4*)(asrc + s * 4);
        float4 e;
        e.x = as.x + ad.x; e.x = e.x > 0.f ? e.x : 0.2f * e.x;
        e.y = as.y + ad.y; e.y = e.y > 0.f ? e.y : 0.2f * e.y;
        e.z = as.z + ad.z; e.z = e.z > 0.f ? e.z : 0.2f * e.z;
        e.w = as.w + ad.w; e.w = e.w > 0.f ? e.w : 0.2f * e.w;
        float w[4];
        w[0] = __expf(e.x); w[1] = __expf(e.y); w[2] = __expf(e.z); w[3] = __expf(e.w);
        ssum.x += w[0]; ssum.y += w[1]; ssum.z += w[2]; ssum.w += w[3];

        const __half* sp = xl + (size_t)s * 1024 + lane * 8;
        #pragma unroll
        for (int h = 0; h < 4; h++) {
            uint4 raw = *(const uint4*)(sp + h * 256);
            __half2* hh = (__half2*)&raw;
            float2 p0 = __half22float2(hh[0]);
            float2 p1 = __half22float2(hh[1]);
            float2 p2 = __half22float2(hh[2]);
            float2 p3 = __half22float2(hh[3]);
            u[h][0] += w[h] * p0.x; u[h][1] += w[h] * p0.y;
            u[h][2] += w[h] * p1.x; u[h][3] += w[h] * p1.y;
            u[h][4] += w[h] * p2.x; u[h][5] += w[h] * p2.y;
            u[h][6] += w[h] * p3.x; u[h][7] += w[h] * p3.y;
        }
    }

    float i0 = 0.25f / (ssum.x + 1e-16f);
    float i1 = 0.25f / (ssum.y + 1e-16f);
    float i2 = 0.25f / (ssum.z + 1e-16f);
    float i3 = 0.25f / (ssum.w + 1e-16f);

    size_t base = (size_t)n * 256 + lane * 8;
    float4 r0 = *(const float4*)(h2 + base);
    float4 r1 = *(const float4*)(h2 + base + 4);
    float o[8];
    o[0] = r0.x + i0*u[0][0] + i1*u[1][0] + i2*u[2][0] + i3*u[3][0];
    o[1] = r0.y + i0*u[0][1] + i1*u[1][1] + i2*u[2][1] + i3*u[3][1];
    o[2] = r0.z + i0*u[0][2] + i1*u[1][2] + i2*u[2][2] + i3*u[3][2];
    o[3] = r0.w + i0*u[0][3] + i1*u[1][3] + i2*u[2][3] + i3*u[3][3];
    o[4] = r1.x + i0*u[0][4] + i1*u[1][4] + i2*u[2][4] + i3*u[3][4];
    o[5] = r1.y + i0*u[0][5] + i1*u[1][5] + i2*u[2][5] + i3*u[3][5];
    o[6] = r1.z + i0*u[0][6] + i1*u[1][6] + i2*u[2][6] + i3*u[3][6];
    o[7] = r1.w + i0*u[0][7] + i1*u[1][7] + i2*u[2][7] + i3*u[3][7];
    __half2 ho[4];
    ho[0] = __floats2half2_rn(o[0], o[1]);
    ho[1] = __floats2half2_rn(o[2], o[3]);
    ho[2] = __floats2half2_rn(o[4], o[5]);
    ho[3] = __floats2half2_rn(o[6], o[7]);
    *(uint4*)(out_at + base) = *(uint4*)ho;
}

// ---------------- output heads ----------------------------------------------
__global__ __launch_bounds__(256) void heads_kernel(
    const float* __restrict__ fc,
    const float* __restrict__ Wb, const float* __restrict__ bb,
    const float* __restrict__ Ws, const float* __restrict__ bs,
    float* __restrict__ out)
{
    int n = blockIdx.x * 8 + (threadIdx.x >> 5);
    if (n >= N_NODES) return;
    int lane = threadIdx.x & 31;

    float acc[7] = {0.f, 0.f, 0.f, 0.f, 0.f, 0.f, 0.f};
    #pragma unroll
    for (int i = 0; i < 8; i++) {
        int k = i * 32 + lane;
        float v = fc[(size_t)n * 256 + k];
        acc[0] += v * Wb[k * 2 + 0];
        acc[1] += v * Wb[k * 2 + 1];
        #pragma unroll
        for (int j = 0; j < 5; j++) acc[2 + j] += v * Ws[k * 5 + j];
    }
    #pragma unroll
    for (int off = 16; off > 0; off >>= 1) {
        #pragma unroll
        for (int j = 0; j < 7; j++) acc[j] += __shfl_xor_sync(0xffffffffu, acc[j], off);
    }
    if (lane == 0) {
        out[(size_t)n * 2 + 0] = acc[0] + bb[0];
        out[(size_t)n * 2 + 1] = acc[1] + bb[1];
        float* sev = out + (size_t)N_NODES * 2 + (size_t)n * 5;
        #pragma unroll
        for (int j = 0; j < 5; j++) sev[j] = acc[2 + j] + bs[j];
    }
}

// ---------------- launch ------------------------------------------------------
static inline void cvt(const float* in, __half* out, int n) {
    cvt_fp16_kernel<<<(n / 8 + 255) / 256, 256>>>(in, out, n);
}
static inline void cvtT(const float* W, __half* out, int K, int N) {
    dim3 grid(N / 32, K / 32);
    cvt_fp16_transpose_kernel<<<grid, dim3(32, 8)>>>(W, out, K, N);
}

extern "C" void kernel_launch(void* const* d_in, const int* in_sizes, int n_in,
                              void* d_out, int out_size)
{
    const float* x        = (const float*)d_in[0];
    const int*   ei       = (const int*)d_in[1];
    const float* W1       = (const float*)d_in[2];
    const float* att_src1 = (const float*)d_in[3];
    const float* att_dst1 = (const float*)d_in[4];
    const float* Wres1    = (const float*)d_in[5];
    const float* b1       = (const float*)d_in[6];
    const float* W2       = (const float*)d_in[7];
    const float* att_src2 = (const float*)d_in[8];
    const float* att_dst2 = (const float*)d_in[9];
    const float* Wres2    = (const float*)d_in[10];
    const float* b2       = (const float*)d_in[11];
    const float* Wfc      = (const float*)d_in[12];
    const float* bfc      = (const float*)d_in[13];
    const float* Wb       = (const float*)d_in[14];
    const float* bb       = (const float*)d_in[15];
    const float* Ws       = (const float*)d_in[16];
    const float* bs       = (const float*)d_in[17];
    float* out = (float*)d_out;

    const int* src = ei;
    const int* dst = ei + N_EDGES;

    float *h1, *h2, *fc2, *asrc, *adst;
    __half *xl16, *at, *wt, *fc1h;
    int *deg, *off, *cur, *esrc;
    cudaGetSymbolAddress((void**)&xl16, g_xl16);
    cudaGetSymbolAddress((void**)&h1,   g_h1);
    cudaGetSymbolAddress((void**)&h2,   g_h2);
    cudaGetSymbolAddress((void**)&fc1h, g_fc1h);
    cudaGetSymbolAddress((void**)&fc2,  g_fc2);
    cudaGetSymbolAddress((void**)&at,   g_at);
    cudaGetSymbolAddress((void**)&wt,   g_wt);
    cudaGetSymbolAddress((void**)&asrc, g_asrc);
    cudaGetSymbolAddress((void**)&adst, g_adst);
    cudaGetSymbolAddress((void**)&deg,  g_deg);
    cudaGetSymbolAddress((void**)&off,  g_off);
    cudaGetSymbolAddress((void**)&cur,  g_cur);
    cudaGetSymbolAddress((void**)&esrc, g_esrc);

    static bool attr_done = false;
    if (!attr_done) {
        cudaFuncSetAttribute(mma_gemm_kernel<0>,
                             cudaFuncAttributeMaxDynamicSharedMemorySize, GEMM_SMEM);
        cudaFuncSetAttribute(mma_gemm_kernel<1>,
                             cudaFuncAttributeMaxDynamicSharedMemorySize, GEMM_SMEM);
        attr_done = true;
    }

    const int mRows = (N_NODES + GBM - 1) / GBM;
    const int attnBlocks = (N_NODES * 4 + 7) / 8;
    const int nodeBlocks = (N_NODES + 7) / 8;
    const int edgeBlocks = (N_EDGES + 255) / 256;

    // launches 1-3: operand prep (packed weights: [Wres1^T ; W1^T] = [2048, 768])
    cvt(x, at, N_NODES * 768);
    cvtT(Wres1, wt, 768, 1024);
    cvtT(W1, wt + (size_t)1024 * 768, 768, 1024);

    // launch 4 (ncu window): fused layer1 GEMM, N=2048
    //   cols [0,1024)    -> h1 (fp32) + b1
    //   cols [1024,2048) -> xl16 (fp16)
    {
        dim3 grid(2048 / GBN, mRows);
        mma_gemm_kernel<0><<<grid, 256, GEMM_SMEM>>>(at, wt, b1, nullptr, h1, xl16,
                                                     N_NODES, 2048, 768, 1024);
    }

    // CSR build
    zero_deg_kernel<<<(N_NODES + 255) / 256, 256>>>(deg);
    hist_kernel<<<edgeBlocks, 256>>>(dst, deg);
    scan_kernel<<<1, 256>>>(deg, off, cur);
    scatter_kernel<<<edgeBlocks, 256>>>(src, dst, cur, esrc);

    // ===== layer 1 aggregation -> fp16 'at' =====
    attn_scores_kernel<<<attnBlocks, 256>>>(xl16, att_src1, att_dst1, asrc, adst);
    gat_aggregate1_kernel<<<attnBlocks, 256>>>(off, esrc, xl16, asrc, adst, h1, at);

    // ===== fused layer2 GEMM, N=1280: cols [0,256)->h2+b2, [256,1280)->xl16 ===
    cvtT(Wres2, wt, 1024, 256);
    cvtT(W2, wt + (size_t)256 * 1024, 1024, 1024);
    {
        dim3 grid(1280 / GBN, mRows);
        mma_gemm_kernel<0><<<grid, 256, GEMM_SMEM>>>(at, wt, b2, nullptr, h2, xl16,
                                                     N_NODES, 1280, 1024, 256);
    }
    attn_scores_kernel<<<attnBlocks, 256>>>(xl16, att_src2, att_dst2, asrc, adst);
    gat_aggregate2_kernel<<<nodeBlocks, 256>>>(off, esrc, xl16, asrc, adst, h2, at);

    // ===== shared FC twice =====
    cvtT(Wfc, wt, 256, 256);
    {
        dim3 grid(256 / GBN, mRows);
        // fc1: all columns fp16 out with bias+leaky (region B, Nsplit=0)
        mma_gemm_kernel<1><<<grid, 256, GEMM_SMEM>>>(at, wt, nullptr, bfc, nullptr, fc1h,
                                                     N_NODES, 256, 256, 0);
        // fc2: all columns fp32 out with bias (region A, Nsplit=256)
        mma_gemm_kernel<0><<<grid, 256, GEMM_SMEM>>>(fc1h, wt, bfc, nullptr, fc2, nullptr,
                                                     N_NODES, 256, 256, 256);
    }

    // ===== heads =====
    heads_kernel<<<nodeBlocks, 256>>>(fc2, Wb, bb, Ws, bs, out);
}

// round 13
// speedup vs baseline: 1.1997x; 1.1012x over previous
#include <cuda_runtime.h>
#include <cuda_fp16.h>
#include <cstdint>

#define N_NODES 20000
#define N_EDGES 320000

// ---------------- scratch (device globals; no allocation allowed) ----------
__device__ __half g_xl16[N_NODES * 1024];  // fp16 per-head features (gather source)
__device__ float  g_h1[N_NODES * 1024];    // layer1 residual GEMM output (read once)
__device__ float  g_h2[N_NODES * 256];     // layer2 residual GEMM output (read once)
__device__ __half g_fc1h[N_NODES * 256];   // fp16 fc1 output
__device__ float  g_fc2[N_NODES * 256];
__device__ __half g_at[N_NODES * 1024];    // fp16 A operand (x, then h1, then h2)
__device__ __half g_wt[2048 * 1024];       // fp16 transposed packed weights [N,K]
__device__ float  g_asrc[N_NODES * 4];
__device__ float  g_adst[N_NODES * 4];
__device__ int    g_deg[N_NODES];
__device__ int    g_off[N_NODES + 1];
__device__ int    g_cur[N_NODES];
__device__ int    g_esrc[N_EDGES];         // src node of each edge, grouped by dst

// ---------------- helpers ---------------------------------------------------
__device__ __forceinline__ void mma_f16(float* d, const unsigned* a, const unsigned* b) {
    asm volatile(
        "mma.sync.aligned.m16n8k16.row.col.f32.f16.f16.f32 "
        "{%0,%1,%2,%3}, {%4,%5,%6,%7}, {%8,%9}, {%0,%1,%2,%3};"
        : "+f"(d[0]), "+f"(d[1]), "+f"(d[2]), "+f"(d[3])
        : "r"(a[0]), "r"(a[1]), "r"(a[2]), "r"(a[3]), "r"(b[0]), "r"(b[1]));
}

__device__ __forceinline__ void ldsm4(unsigned& r0, unsigned& r1, unsigned& r2, unsigned& r3,
                                      uint32_t addr) {
    asm volatile("ldmatrix.sync.aligned.m8n8.x4.shared.b16 {%0,%1,%2,%3}, [%4];"
                 : "=r"(r0), "=r"(r1), "=r"(r2), "=r"(r3) : "r"(addr));
}

__device__ __forceinline__ void cp16(void* smem, const void* gmem, bool pred) {
    unsigned sa = (unsigned)__cvta_generic_to_shared(smem);
    int sz = pred ? 16 : 0;
    asm volatile("cp.async.cg.shared.global [%0], [%1], 16, %2;"
                 :: "r"(sa), "l"(gmem), "r"(sz));
}

// ---------------- fp16 conversion passes -------------------------------------
__global__ void cvt_fp16_kernel(const float* __restrict__ in, __half* __restrict__ out, int n) {
    int i = (blockIdx.x * blockDim.x + threadIdx.x) * 8;
    if (i >= n) return;
    float4 v0 = *(const float4*)(in + i);
    float4 v1 = *(const float4*)(in + i + 4);
    __half2 h[4];
    h[0] = __floats2half2_rn(v0.x, v0.y);
    h[1] = __floats2half2_rn(v0.z, v0.w);
    h[2] = __floats2half2_rn(v1.x, v1.y);
    h[3] = __floats2half2_rn(v1.z, v1.w);
    *(uint4*)(out + i) = *(uint4*)h;
}

// weights: W[K,N] fp32 -> out[N,K] fp16 (transposed). K,N multiples of 32.
__global__ void cvt_fp16_transpose_kernel(const float* __restrict__ in, __half* __restrict__ out,
                                          int K, int N) {
    __shared__ float t[32][33];
    int k0 = blockIdx.y * 32, n0 = blockIdx.x * 32;
    int tx = threadIdx.x, ty = threadIdx.y;  // 32 x 8
    #pragma unroll
    for (int j = 0; j < 32; j += 8)
        t[ty + j][tx] = in[(size_t)(k0 + ty + j) * N + n0 + tx];
    __syncthreads();
    #pragma unroll
    for (int j = 0; j < 32; j += 8)
        out[(size_t)(n0 + ty + j) * K + k0 + tx] = __float2half_rn(t[tx][ty + j]);
}

// ---------------- CSR build ---------------------------------------------------
__global__ void zero_deg_kernel(int* __restrict__ deg) {
    int i = blockIdx.x * blockDim.x + threadIdx.x;
    if (i < N_NODES) deg[i] = 0;
}

__global__ void hist_kernel(const int* __restrict__ dst, int* __restrict__ deg) {
    int e = blockIdx.x * blockDim.x + threadIdx.x;
    if (e < N_EDGES) atomicAdd(&deg[dst[e]], 1);
}

__global__ __launch_bounds__(256) void scan_kernel(
    const int* __restrict__ deg, int* __restrict__ off, int* __restrict__ cur)
{
    __shared__ int partial[256];
    const int tid = threadIdx.x;
    const int CH = (N_NODES + 255) / 256;
    const int base = tid * CH;

    int s = 0;
    for (int j = 0; j < CH; j++) {
        int i = base + j;
        if (i < N_NODES) s += deg[i];
    }
    partial[tid] = s;
    __syncthreads();
    for (int o = 1; o < 256; o <<= 1) {
        int v = (tid >= o) ? partial[tid - o] : 0;
        __syncthreads();
        partial[tid] += v;
        __syncthreads();
    }
    int run = partial[tid] - s;
    for (int j = 0; j < CH; j++) {
        int i = base + j;
        if (i < N_NODES) {
            off[i] = run;
            cur[i] = run;
            run += deg[i];
        }
    }
    if (tid == 255) off[N_NODES] = run;
}

__global__ void scatter_kernel(const int* __restrict__ src, const int* __restrict__ dst,
                               int* __restrict__ cur, int* __restrict__ esrc) {
    int e = blockIdx.x * blockDim.x + threadIdx.x;
    if (e >= N_EDGES) return;
    int pos = atomicAdd(&cur[dst[e]], 1);
    esrc[pos] = src[e];
}

// ---------------- fp16 tensor-core GEMM, cp.async 4-stage, single-sync -------
// C_all[M,N] = A[M,K] @ Bt[N,K]^T. Split output: columns [0,Nsplit) go fp32 to
// C (row stride Nsplit, bias biasA); columns [Nsplit,N) go fp16 to C16 (row
// stride N-Nsplit, bias biasB). Nsplit % 128 == 0 so each CTA is in one region.
// CTA tile 128x128, K-tile 32 halves (80B row pitch, ldmatrix conflict-free),
// 8 warps (2x4) 64x32, mma m16n8k16, single sync per k-tile.
// Requires N % 128 == 0, K % 32 == 0; M guarded.
#define GBM 128
#define GBN 128
#define HK 32
#define ROWW 20
#define TSZW (128 * ROWW)
#define STAGES 4
#define GEMM_SMEM (STAGES * 2 * TSZW * 4)   // 81920 bytes

template <int ACT>  // 0: none, 1: leaky_relu(0.01)
__global__ __launch_bounds__(256, 2) void mma_gemm_kernel(
    const __half* __restrict__ A, const __half* __restrict__ Bt,
    const float* __restrict__ biasA, const float* __restrict__ biasB,
    float* __restrict__ C, __half* __restrict__ C16,
    int M, int N, int K, int Nsplit)
{
    extern __shared__ unsigned smem[];
    unsigned* As = smem;
    unsigned* Bs = smem + STAGES * TSZW;

    const int tid = threadIdx.x;
    const int warp = tid >> 5, lane = tid & 31;
    const int g = lane >> 2, tg = lane & 3;
    const int wr = (warp >> 2) * 64;
    const int wc = (warp & 3) * 32;

    const int bm = blockIdx.y, bn = blockIdx.x;

    const int rowS = tid >> 1;
    const int rowA = bm * GBM + rowS;
    const bool avalid = rowA < M;
    const __half* Ap = avalid ? (A + (size_t)rowA * K + (tid & 1) * 16) : A;
    const __half* Bp = Bt + (size_t)(bn * GBN + rowS) * K + (tid & 1) * 16;
    const int sOff = rowS * ROWW + (tid & 1) * 8;

    // ldmatrix per-lane byte offsets within a tile (80B row pitch)
    const uint32_t sbase = (uint32_t)__cvta_generic_to_shared(smem);
    const uint32_t aLds = (uint32_t)(wr + (lane & 15)) * 80u + ((lane >> 4) & 1) * 16u;
    const uint32_t bLds = (uint32_t)(wc + ((lane >> 4) & 1) * 8 + (lane & 7)) * 80u
                        + ((lane >> 3) & 1) * 16u;

    const int KT = K / HK;

    float acc[4][4][4];
    #pragma unroll
    for (int mt = 0; mt < 4; mt++)
        #pragma unroll
        for (int nt = 0; nt < 4; nt++)
            #pragma unroll
            for (int i = 0; i < 4; i++) acc[mt][nt][i] = 0.0f;

    // prologue: stage tiles 0..STAGES-2
    #pragma unroll
    for (int kt = 0; kt < STAGES - 1; kt++) {
        if (kt < KT) {
            unsigned* as = As + (kt % STAGES) * TSZW;
            unsigned* bs = Bs + (kt % STAGES) * TSZW;
            const __half* ap = Ap + (avalid ? kt * HK : 0);
            const __half* bp = Bp + kt * HK;
            cp16(&as[sOff],     ap,     avalid);
            cp16(&as[sOff + 4], ap + 8, avalid);
            cp16(&bs[sOff],     bp,     true);
            cp16(&bs[sOff + 4], bp + 8, true);
        }
        asm volatile("cp.async.commit_group;");
    }

    for (int kt = 0; kt < KT; kt++) {
        // tile kt resident
        asm volatile("cp.async.wait_group %0;" :: "n"(STAGES - 2));
        // single barrier: also proves all warps finished reading buffer
        // (kt-1)%STAGES == (kt+STAGES-1)%STAGES before we overwrite it below
        __syncthreads();

        int kf = kt + STAGES - 1;
        if (kf < KT) {
            unsigned* as = As + (kf % STAGES) * TSZW;
            unsigned* bs = Bs + (kf % STAGES) * TSZW;
            const __half* ap = Ap + (avalid ? kf * HK : 0);
            const __half* bp = Bp + kf * HK;
            cp16(&as[sOff],     ap,     avalid);
            cp16(&as[sOff + 4], ap + 8, avalid);
            cp16(&bs[sOff],     bp,     true);
            cp16(&bs[sOff + 4], bp + 8, true);
        }
        asm volatile("cp.async.commit_group;");

        const uint32_t aBase = sbase + (uint32_t)((kt % STAGES) * TSZW) * 4u + aLds;
        const uint32_t bBase = sbase + (uint32_t)((STAGES + (kt % STAGES)) * TSZW) * 4u + bLds;

        #pragma unroll
        for (int kk = 0; kk < 2; kk++) {
            unsigned af[4][4];
            unsigned bf[4][2];
            #pragma unroll
            for (int mt = 0; mt < 4; mt++)
                ldsm4(af[mt][0], af[mt][1], af[mt][2], af[mt][3],
                      aBase + mt * 1280u + kk * 32u);
            #pragma unroll
            for (int p = 0; p < 2; p++)
                ldsm4(bf[p * 2][0], bf[p * 2][1], bf[p * 2 + 1][0], bf[p * 2 + 1][1],
                      bBase + p * 1280u + kk * 32u);
            #pragma unroll
            for (int mt = 0; mt < 4; mt++)
                #pragma unroll
                for (int nt = 0; nt < 4; nt++)
                    mma_f16(acc[mt][nt], af[mt], bf[nt]);
        }
    }

    // epilogue: whole CTA tile lies in one output region
    const int colBase = bn * GBN;
    const bool rA = colBase < Nsplit;
    const int Wd = rA ? Nsplit : (N - Nsplit);
    const int cb = (rA ? colBase : colBase - Nsplit) + wc;
    const float* bias = rA ? biasA : biasB;

    float bv[4][2];
    #pragma unroll
    for (int nt = 0; nt < 4; nt++) {
        int col = cb + nt * 8 + 2 * tg;
        bv[nt][0] = bias ? bias[col] : 0.0f;
        bv[nt][1] = bias ? bias[col + 1] : 0.0f;
    }

    #pragma unroll
    for (int mt = 0; mt < 4; mt++) {
        #pragma unroll
        for (int i = 0; i < 2; i++) {
            int row = bm * GBM + wr + mt * 16 + g + i * 8;
            if (row >= M) continue;
            size_t rb = (size_t)row * Wd + cb;
            #pragma unroll
            for (int nt = 0; nt < 4; nt++) {
                float2 v;
                v.x = acc[mt][nt][i * 2 + 0] + bv[nt][0];
                v.y = acc[mt][nt][i * 2 + 1] + bv[nt][1];
                if (ACT == 1) {
                    v.x = v.x > 0.f ? v.x : 0.01f * v.x;
                    v.y = v.y > 0.f ? v.y : 0.01f * v.y;
                }
                if (rA) *(float2*)(C + rb + nt * 8 + 2 * tg) = v;
                else    *(__half2*)(C16 + rb + nt * 8 + 2 * tg) = __floats2half2_rn(v.x, v.y);
            }
        }
    }
}

// ---------------- attention scores (fp16 xl) ---------------------------------
__global__ __launch_bounds__(256) void attn_scores_kernel(
    const __half* __restrict__ xl,
    const float* __restrict__ att_src, const float* __restrict__ att_dst,
    float* __restrict__ asrc, float* __restrict__ adst)
{
    int task = blockIdx.x * 8 + (threadIdx.x >> 5);
    if (task >= N_NODES * 4) return;
    int lane = threadIdx.x & 31;
    int n = task >> 2, h = task & 3;

    const __half* xp = xl + (size_t)n * 1024 + h * 256 + lane * 8;
    const float* sp = att_src + h * 256 + lane * 8;
    const float* dp = att_dst + h * 256 + lane * 8;

    uint4 raw = *(const uint4*)xp;
    __half2* hh = (__half2*)&raw;
    float2 p0 = __half22float2(hh[0]);
    float2 p1 = __half22float2(hh[1]);
    float2 p2 = __half22float2(hh[2]);
    float2 p3 = __half22float2(hh[3]);
    float4 a0 = *(const float4*)(sp), a1 = *(const float4*)(sp + 4);
    float4 b0 = *(const float4*)(dp), b1 = *(const float4*)(dp + 4);

    float s1 = p0.x*a0.x + p0.y*a0.y + p1.x*a0.z + p1.y*a0.w
             + p2.x*a1.x + p2.y*a1.y + p3.x*a1.z + p3.y*a1.w;
    float s2 = p0.x*b0.x + p0.y*b0.y + p1.x*b0.z + p1.y*b0.w
             + p2.x*b1.x + p2.y*b1.y + p3.x*b1.z + p3.y*b1.w;

    #pragma unroll
    for (int off = 16; off > 0; off >>= 1) {
        s1 += __shfl_xor_sync(0xffffffffu, s1, off);
        s2 += __shfl_xor_sync(0xffffffffu, s2, off);
    }
    if (lane == 0) {
        asrc[task] = s1;
        adst[task] = s2;
    }
}

// ---------------- layer1 aggregation: fp16 gather, fp16 'at' output ----------
__global__ __launch_bounds__(256) void gat_aggregate1_kernel(
    const int* __restrict__ off, const int* __restrict__ esrc,
    const __half* __restrict__ xl, const float* __restrict__ asrc,
    const float* __restrict__ adst, const float* __restrict__ h1,
    __half* __restrict__ out_at)
{
    int task = blockIdx.x * 8 + (threadIdx.x >> 5);
    if (task >= N_NODES * 4) return;
    int lane = threadIdx.x & 31;
    int n = task >> 2, h = task & 3;

    const float ad = adst[n * 4 + h];
    const int j0 = off[n], j1 = off[n + 1];

    float u[8] = {0.f, 0.f, 0.f, 0.f, 0.f, 0.f, 0.f, 0.f};
    float ssum = 0.f;

    for (int j = j0; j < j1; j++) {
        int s = esrc[j];
        float a = asrc[s * 4 + h] + ad;
        a = a > 0.f ? a : 0.2f * a;
        float w = __expf(a);
        ssum += w;
        uint4 raw = *(const uint4*)(xl + (size_t)s * 1024 + h * 256 + lane * 8);
        __half2* hh = (__half2*)&raw;
        float2 p0 = __half22float2(hh[0]);
        float2 p1 = __half22float2(hh[1]);
        float2 p2 = __half22float2(hh[2]);
        float2 p3 = __half22float2(hh[3]);
        u[0] += w * p0.x; u[1] += w * p0.y; u[2] += w * p1.x; u[3] += w * p1.y;
        u[4] += w * p2.x; u[5] += w * p2.y; u[6] += w * p3.x; u[7] += w * p3.y;
    }

    float inv = 1.0f / (ssum + 1e-16f);
    size_t base = (size_t)n * 1024 + h * 256 + lane * 8;
    float4 r0 = *(const float4*)(h1 + base);
    float4 r1 = *(const float4*)(h1 + base + 4);
    __half2 o[4];
    o[0] = __floats2half2_rn(r0.x + u[0] * inv, r0.y + u[1] * inv);
    o[1] = __floats2half2_rn(r0.z + u[2] * inv, r0.w + u[3] * inv);
    o[2] = __floats2half2_rn(r1.x + u[4] * inv, r1.y + u[5] * inv);
    o[3] = __floats2half2_rn(r1.z + u[6] * inv, r1.w + u[7] * inv);
    *(uint4*)(out_at + base) = *(uint4*)o;
}

// ---------------- layer2 aggregation: head-mean, fp16 gather/out -------------
__global__ __launch_bounds__(256) void gat_aggregate2_kernel(
    const int* __restrict__ off, const int* __restrict__ esrc,
    const __half* __restrict__ xl, const float* __restrict__ asrc,
    const float* __restrict__ adst, const float* __restrict__ h2,
    __half* __restrict__ out_at)
{
    int n = blockIdx.x * 8 + (threadIdx.x >> 5);
    if (n >= N_NODES) return;
    int lane = threadIdx.x & 31;

    float4 ad = *(const float4*)(adst + n * 4);
    const int j0 = off[n], j1 = off[n + 1];

    float u[4][8];
    #pragma unroll
    for (int h = 0; h < 4; h++)
        #pragma unroll
        for (int q = 0; q < 8; q++) u[h][q] = 0.f;
    float4 ssum = make_float4(0.f, 0.f, 0.f, 0.f);

    for (int j = j0; j < j1; j++) {
        int s = esrc[j];
        float4 as = *(const float4*)(asrc + s * 4);
        float4 e;
        e.x = as.x + ad.x; e.x = e.x > 0.f ? e.x : 0.2f * e.x;
        e.y = as.y + ad.y; e.y = e.y > 0.f ? e.y : 0.2f * e.y;
        e.z = as.z + ad.z; e.z = e.z > 0.f ? e.z : 0.2f * e.z;
        e.w = as.w + ad.w; e.w = e.w > 0.f ? e.w : 0.2f * e.w;
        float w[4];
        w[0] = __expf(e.x); w[1] = __expf(e.y); w[2] = __expf(e.z); w[3] = __expf(e.w);
        ssum.x += w[0]; ssum.y += w[1]; ssum.z += w[2]; ssum.w += w[3];

        const __half* sp = xl + (size_t)s * 1024 + lane * 8;
        #pragma unroll
        for (int h = 0; h < 4; h++) {
            uint4 raw = *(const uint4*)(sp + h * 256);
            __half2* hh = (__half2*)&raw;
            float2 p0 = __half22float2(hh[0]);
            float2 p1 = __half22float2(hh[1]);
            float2 p2 = __half22float2(hh[2]);
            float2 p3 = __half22float2(hh[3]);
            u[h][0] += w[h] * p0.x; u[h][1] += w[h] * p0.y;
            u[h][2] += w[h] * p1.x; u[h][3] += w[h] * p1.y;
            u[h][4] += w[h] * p2.x; u[h][5] += w[h] * p2.y;
            u[h][6] += w[h] * p3.x; u[h][7] += w[h] * p3.y;
        }
    }

    float i0 = 0.25f / (ssum.x + 1e-16f);
    float i1 = 0.25f / (ssum.y + 1e-16f);
    float i2 = 0.25f / (ssum.z + 1e-16f);
    float i3 = 0.25f / (ssum.w + 1e-16f);

    size_t base = (size_t)n * 256 + lane * 8;
    float4 r0 = *(const float4*)(h2 + base);
    float4 r1 = *(const float4*)(h2 + base + 4);
    float o[8];
    o[0] = r0.x + i0*u[0][0] + i1*u[1][0] + i2*u[2][0] + i3*u[3][0];
    o[1] = r0.y + i0*u[0][1] + i1*u[1][1] + i2*u[2][1] + i3*u[3][1];
    o[2] = r0.z + i0*u[0][2] + i1*u[1][2] + i2*u[2][2] + i3*u[3][2];
    o[3] = r0.w + i0*u[0][3] + i1*u[1][3] + i2*u[2][3] + i3*u[3][3];
    o[4] = r1.x + i0*u[0][4] + i1*u[1][4] + i2*u[2][4] + i3*u[3][4];
    o[5] = r1.y + i0*u[0][5] + i1*u[1][5] + i2*u[2][5] + i3*u[3][5];
    o[6] = r1.z + i0*u[0][6] + i1*u[1][6] + i2*u[2][6] + i3*u[3][6];
    o[7] = r1.w + i0*u[0][7] + i1*u[1][7] + i2*u[2][7] + i3*u[3][7];
    __half2 ho[4];
    ho[0] = __floats2half2_rn(o[0], o[1]);
    ho[1] = __floats2half2_rn(o[2], o[3]);
    ho[2] = __floats2half2_rn(o[4], o[5]);
    ho[3] = __floats2half2_rn(o[6], o[7]);
    *(uint4*)(out_at + base) = *(uint4*)ho;
}

// ---------------- output heads ----------------------------------------------
__global__ __launch_bounds__(256) void heads_kernel(
    const float* __restrict__ fc,
    const float* __restrict__ Wb, const float* __restrict__ bb,
    const float* __restrict__ Ws, const float* __restrict__ bs,
    float* __restrict__ out)
{
    int n = blockIdx.x * 8 + (threadIdx.x >> 5);
    if (n >= N_NODES) return;
    int lane = threadIdx.x & 31;

    float acc[7] = {0.f, 0.f, 0.f, 0.f, 0.f, 0.f, 0.f};
    #pragma unroll
    for (int i = 0; i < 8; i++) {
        int k = i * 32 + lane;
        float v = fc[(size_t)n * 256 + k];
        acc[0] += v * Wb[k * 2 + 0];
        acc[1] += v * Wb[k * 2 + 1];
        #pragma unroll
        for (int j = 0; j < 5; j++) acc[2 + j] += v * Ws[k * 5 + j];
    }
    #pragma unroll
    for (int off = 16; off > 0; off >>= 1) {
        #pragma unroll
        for (int j = 0; j < 7; j++) acc[j] += __shfl_xor_sync(0xffffffffu, acc[j], off);
    }
    if (lane == 0) {
        out[(size_t)n * 2 + 0] = acc[0] + bb[0];
        out[(size_t)n * 2 + 1] = acc[1] + bb[1];
        float* sev = out + (size_t)N_NODES * 2 + (size_t)n * 5;
        #pragma unroll
        for (int j = 0; j < 5; j++) sev[j] = acc[2 + j] + bs[j];
    }
}

// ---------------- launch ------------------------------------------------------
static inline void cvt(const float* in, __half* out, int n, cudaStream_t st = 0) {
    cvt_fp16_kernel<<<(n / 8 + 255) / 256, 256, 0, st>>>(in, out, n);
}
static inline void cvtT(const float* W, __half* out, int K, int N, cudaStream_t st = 0) {
    dim3 grid(N / 32, K / 32);
    cvt_fp16_transpose_kernel<<<grid, dim3(32, 8), 0, st>>>(W, out, K, N);
}

extern "C" void kernel_launch(void* const* d_in, const int* in_sizes, int n_in,
                              void* d_out, int out_size)
{
    const float* x        = (const float*)d_in[0];
    const int*   ei       = (const int*)d_in[1];
    const float* W1       = (const float*)d_in[2];
    const float* att_src1 = (const float*)d_in[3];
    const float* att_dst1 = (const float*)d_in[4];
    const float* Wres1    = (const float*)d_in[5];
    const float* b1       = (const float*)d_in[6];
    const float* W2       = (const float*)d_in[7];
    const float* att_src2 = (const float*)d_in[8];
    const float* att_dst2 = (const float*)d_in[9];
    const float* Wres2    = (const float*)d_in[10];
    const float* b2       = (const float*)d_in[11];
    const float* Wfc      = (const float*)d_in[12];
    const float* bfc      = (const float*)d_in[13];
    const float* Wb       = (const float*)d_in[14];
    const float* bb       = (const float*)d_in[15];
    const float* Ws       = (const float*)d_in[16];
    const float* bs       = (const float*)d_in[17];
    float* out = (float*)d_out;

    const int* src = ei;
    const int* dst = ei + N_EDGES;

    float *h1, *h2, *fc2, *asrc, *adst;
    __half *xl16, *at, *wt, *fc1h;
    int *deg, *off, *cur, *esrc;
    cudaGetSymbolAddress((void**)&xl16, g_xl16);
    cudaGetSymbolAddress((void**)&h1,   g_h1);
    cudaGetSymbolAddress((void**)&h2,   g_h2);
    cudaGetSymbolAddress((void**)&fc1h, g_fc1h);
    cudaGetSymbolAddress((void**)&fc2,  g_fc2);
    cudaGetSymbolAddress((void**)&at,   g_at);
    cudaGetSymbolAddress((void**)&wt,   g_wt);
    cudaGetSymbolAddress((void**)&asrc, g_asrc);
    cudaGetSymbolAddress((void**)&adst, g_adst);
    cudaGetSymbolAddress((void**)&deg,  g_deg);
    cudaGetSymbolAddress((void**)&off,  g_off);
    cudaGetSymbolAddress((void**)&cur,  g_cur);
    cudaGetSymbolAddress((void**)&esrc, g_esrc);

    static bool init_done = false;
    static cudaStream_t s1;
    static cudaEvent_t ev0, evCsr, evGemm1, evW2, evGemm2, evWfc;
    if (!init_done) {
        cudaFuncSetAttribute(mma_gemm_kernel<0>,
                             cudaFuncAttributeMaxDynamicSharedMemorySize, GEMM_SMEM);
        cudaFuncSetAttribute(mma_gemm_kernel<1>,
                             cudaFuncAttributeMaxDynamicSharedMemorySize, GEMM_SMEM);
        cudaStreamCreateWithFlags(&s1, cudaStreamNonBlocking);
        cudaEventCreateWithFlags(&ev0,    cudaEventDisableTiming);
        cudaEventCreateWithFlags(&evCsr,  cudaEventDisableTiming);
        cudaEventCreateWithFlags(&evGemm1, cudaEventDisableTiming);
        cudaEventCreateWithFlags(&evW2,   cudaEventDisableTiming);
        cudaEventCreateWithFlags(&evGemm2, cudaEventDisableTiming);
        cudaEventCreateWithFlags(&evWfc,  cudaEventDisableTiming);
        init_done = true;
    }

    const int mRows = (N_NODES + GBM - 1) / GBM;
    const int attnBlocks = (N_NODES * 4 + 7) / 8;
    const int nodeBlocks = (N_NODES + 7) / 8;
    const int edgeBlocks = (N_EDGES + 255) / 256;

    // fork side stream from main
    cudaEventRecord(ev0, 0);
    cudaStreamWaitEvent(s1, ev0, 0);

    // ---- side stream: CSR build (independent of GEMM chain) ----
    zero_deg_kernel<<<(N_NODES + 255) / 256, 256, 0, s1>>>(deg);
    hist_kernel<<<edgeBlocks, 256, 0, s1>>>(dst, deg);
    scan_kernel<<<1, 256, 0, s1>>>(deg, off, cur);
    scatter_kernel<<<edgeBlocks, 256, 0, s1>>>(src, dst, cur, esrc);
    cudaEventRecord(evCsr, s1);

    // ---- main: operand prep + fused layer1 GEMM ----
    cvt(x, at, N_NODES * 768);
    cvtT(Wres1, wt, 768, 1024);
    cvtT(W1, wt + (size_t)1024 * 768, 768, 1024);
    {
        dim3 grid(2048 / GBN, mRows);
        mma_gemm_kernel<0><<<grid, 256, GEMM_SMEM>>>(at, wt, b1, nullptr, h1, xl16,
                                                     N_NODES, 2048, 768, 1024);
    }
    cudaEventRecord(evGemm1, 0);

    // ---- side stream: layer2 weight conversions (after GEMM1 done with wt) ----
    cudaStreamWaitEvent(s1, evGemm1, 0);
    cvtT(Wres2, wt, 1024, 256, s1);
    cvtT(W2, wt + (size_t)256 * 1024, 1024, 1024, s1);
    cudaEventRecord(evW2, s1);

    // ---- main: layer 1 aggregation -> fp16 'at' ----
    attn_scores_kernel<<<attnBlocks, 256>>>(xl16, att_src1, att_dst1, asrc, adst);
    cudaStreamWaitEvent(0, evCsr, 0);
    gat_aggregate1_kernel<<<attnBlocks, 256>>>(off, esrc, xl16, asrc, adst, h1, at);

    // ---- main: fused layer2 GEMM (needs wt from side stream) ----
    cudaStreamWaitEvent(0, evW2, 0);
    {
        dim3 grid(1280 / GBN, mRows);
        mma_gemm_kernel<0><<<grid, 256, GEMM_SMEM>>>(at, wt, b2, nullptr, h2, xl16,
                                                     N_NODES, 1280, 1024, 256);
    }
    cudaEventRecord(evGemm2, 0);

    // ---- side stream: fc weight conversion ----
    cudaStreamWaitEvent(s1, evGemm2, 0);
    cvtT(Wfc, wt, 256, 256, s1);
    cudaEventRecord(evWfc, s1);

    // ---- main: layer 2 aggregation ----
    attn_scores_kernel<<<attnBlocks, 256>>>(xl16, att_src2, att_dst2, asrc, adst);
    gat_aggregate2_kernel<<<nodeBlocks, 256>>>(off, esrc, xl16, asrc, adst, h2, at);

    // ---- main: shared FC twice ----
    cudaStreamWaitEvent(0, evWfc, 0);
    {
        dim3 grid(256 / GBN, mRows);
        mma_gemm_kernel<1><<<grid, 256, GEMM_SMEM>>>(at, wt, nullptr, bfc, nullptr, fc1h,
                                                     N_NODES, 256, 256, 0);
        mma_gemm_kernel<0><<<grid, 256, GEMM_SMEM>>>(fc1h, wt, bfc, nullptr, fc2, nullptr,
                                                     N_NODES, 256, 256, 256);
    }

    // ---- heads ----
    heads_kernel<<<nodeBlocks, 256>>>(fc2, Wb, bb, Ws, bs, out);
}

// round 14
// speedup vs baseline: 1.1998x; 1.0000x over previous
#include <cuda_runtime.h>
#include <cuda_fp16.h>
#include <cstdint>

#define N_NODES 20000
#define N_EDGES 320000

// ---------------- scratch (device globals; no allocation allowed) ----------
__device__ __half g_xl16[N_NODES * 1024];  // fp16 per-head features (gather source)
__device__ float  g_h1[N_NODES * 1024];    // layer1 residual GEMM output (read once)
__device__ float  g_h2[N_NODES * 256];     // layer2 residual GEMM output (read once)
__device__ __half g_fc1h[N_NODES * 256];   // fp16 fc1 output
__device__ __half g_fc2h[N_NODES * 256];   // fp16 fc2 output
__device__ __half g_at[N_NODES * 1024];    // fp16 A operand (x, then h1, then h2)
__device__ __half g_wt[2048 * 1024];       // fp16 transposed packed weights [N,K]
__device__ float  g_asrc[N_NODES * 4];
__device__ float  g_adst[N_NODES * 4];
__device__ int    g_deg[N_NODES];
__device__ int    g_off[N_NODES + 1];
__device__ int    g_cur[N_NODES];
__device__ int    g_esrc[N_EDGES];         // src node of each edge, grouped by dst

// ---------------- helpers ---------------------------------------------------
__device__ __forceinline__ void mma_f16(float* d, const unsigned* a, const unsigned* b) {
    asm volatile(
        "mma.sync.aligned.m16n8k16.row.col.f32.f16.f16.f32 "
        "{%0,%1,%2,%3}, {%4,%5,%6,%7}, {%8,%9}, {%0,%1,%2,%3};"
        : "+f"(d[0]), "+f"(d[1]), "+f"(d[2]), "+f"(d[3])
        : "r"(a[0]), "r"(a[1]), "r"(a[2]), "r"(a[3]), "r"(b[0]), "r"(b[1]));
}

__device__ __forceinline__ void ldsm4(unsigned& r0, unsigned& r1, unsigned& r2, unsigned& r3,
                                      uint32_t addr) {
    asm volatile("ldmatrix.sync.aligned.m8n8.x4.shared.b16 {%0,%1,%2,%3}, [%4];"
                 : "=r"(r0), "=r"(r1), "=r"(r2), "=r"(r3) : "r"(addr));
}

__device__ __forceinline__ void cp16(void* smem, const void* gmem, bool pred) {
    unsigned sa = (unsigned)__cvta_generic_to_shared(smem);
    int sz = pred ? 16 : 0;
    asm volatile("cp.async.cg.shared.global [%0], [%1], 16, %2;"
                 :: "r"(sa), "l"(gmem), "r"(sz));
}

// ---------------- fp16 conversion passes -------------------------------------
__global__ void cvt_fp16_kernel(const float* __restrict__ in, __half* __restrict__ out, int n) {
    int i = (blockIdx.x * blockDim.x + threadIdx.x) * 8;
    if (i >= n) return;
    float4 v0 = *(const float4*)(in + i);
    float4 v1 = *(const float4*)(in + i + 4);
    __half2 h[4];
    h[0] = __floats2half2_rn(v0.x, v0.y);
    h[1] = __floats2half2_rn(v0.z, v0.w);
    h[2] = __floats2half2_rn(v1.x, v1.y);
    h[3] = __floats2half2_rn(v1.z, v1.w);
    *(uint4*)(out + i) = *(uint4*)h;
}

// weights: W[K,N] fp32 -> out[N,K] fp16 (transposed). K,N multiples of 32.
__global__ void cvt_fp16_transpose_kernel(const float* __restrict__ in, __half* __restrict__ out,
                                          int K, int N) {
    __shared__ float t[32][33];
    int k0 = blockIdx.y * 32, n0 = blockIdx.x * 32;
    int tx = threadIdx.x, ty = threadIdx.y;  // 32 x 8
    #pragma unroll
    for (int j = 0; j < 32; j += 8)
        t[ty + j][tx] = in[(size_t)(k0 + ty + j) * N + n0 + tx];
    __syncthreads();
    #pragma unroll
    for (int j = 0; j < 32; j += 8)
        out[(size_t)(n0 + ty + j) * K + k0 + tx] = __float2half_rn(t[tx][ty + j]);
}

// ---------------- CSR build ---------------------------------------------------
__global__ void zero_deg_kernel(int* __restrict__ deg) {
    int i = blockIdx.x * blockDim.x + threadIdx.x;
    if (i < N_NODES) deg[i] = 0;
}

__global__ void hist_kernel(const int* __restrict__ dst, int* __restrict__ deg) {
    int e = blockIdx.x * blockDim.x + threadIdx.x;
    if (e < N_EDGES) atomicAdd(&deg[dst[e]], 1);
}

__global__ __launch_bounds__(256) void scan_kernel(
    const int* __restrict__ deg, int* __restrict__ off, int* __restrict__ cur)
{
    __shared__ int partial[256];
    const int tid = threadIdx.x;
    const int CH = (N_NODES + 255) / 256;
    const int base = tid * CH;

    int s = 0;
    for (int j = 0; j < CH; j++) {
        int i = base + j;
        if (i < N_NODES) s += deg[i];
    }
    partial[tid] = s;
    __syncthreads();
    for (int o = 1; o < 256; o <<= 1) {
        int v = (tid >= o) ? partial[tid - o] : 0;
        __syncthreads();
        partial[tid] += v;
        __syncthreads();
    }
    int run = partial[tid] - s;
    for (int j = 0; j < CH; j++) {
        int i = base + j;
        if (i < N_NODES) {
            off[i] = run;
            cur[i] = run;
            run += deg[i];
        }
    }
    if (tid == 255) off[N_NODES] = run;
}

__global__ void scatter_kernel(const int* __restrict__ src, const int* __restrict__ dst,
                               int* __restrict__ cur, int* __restrict__ esrc) {
    int e = blockIdx.x * blockDim.x + threadIdx.x;
    if (e >= N_EDGES) return;
    int pos = atomicAdd(&cur[dst[e]], 1);
    esrc[pos] = src[e];
}

// ---------------- fp16 tensor-core GEMM, cp.async 4-stage, single-sync -------
// C_all[M,N] = A[M,K] @ Bt[N,K]^T. Split output: columns [0,Nsplit) go fp32 to
// C (row stride Nsplit, bias biasA); columns [Nsplit,N) go fp16 to C16 (row
// stride N-Nsplit, bias biasB). Nsplit % 128 == 0 so each CTA is in one region.
// CTA tile 128x128, K-tile 32 halves (80B row pitch, ldmatrix conflict-free),
// 8 warps (2x4) 64x32, mma m16n8k16, single sync per k-tile.
// Requires N % 128 == 0, K % 32 == 0; M guarded.
#define GBM 128
#define GBN 128
#define HK 32
#define ROWW 20
#define TSZW (128 * ROWW)
#define STAGES 4
#define GEMM_SMEM (STAGES * 2 * TSZW * 4)   // 81920 bytes

template <int ACT>  // 0: none, 1: leaky_relu(0.01)
__global__ __launch_bounds__(256, 2) void mma_gemm_kernel(
    const __half* __restrict__ A, const __half* __restrict__ Bt,
    const float* __restrict__ biasA, const float* __restrict__ biasB,
    float* __restrict__ C, __half* __restrict__ C16,
    int M, int N, int K, int Nsplit)
{
    extern __shared__ unsigned smem[];
    unsigned* As = smem;
    unsigned* Bs = smem + STAGES * TSZW;

    const int tid = threadIdx.x;
    const int warp = tid >> 5, lane = tid & 31;
    const int g = lane >> 2, tg = lane & 3;
    const int wr = (warp >> 2) * 64;
    const int wc = (warp & 3) * 32;

    const int bm = blockIdx.y, bn = blockIdx.x;

    const int rowS = tid >> 1;
    const int rowA = bm * GBM + rowS;
    const bool avalid = rowA < M;
    const __half* Ap = avalid ? (A + (size_t)rowA * K + (tid & 1) * 16) : A;
    const __half* Bp = Bt + (size_t)(bn * GBN + rowS) * K + (tid & 1) * 16;
    const int sOff = rowS * ROWW + (tid & 1) * 8;

    const uint32_t sbase = (uint32_t)__cvta_generic_to_shared(smem);
    const uint32_t aLds = (uint32_t)(wr + (lane & 15)) * 80u + ((lane >> 4) & 1) * 16u;
    const uint32_t bLds = (uint32_t)(wc + ((lane >> 4) & 1) * 8 + (lane & 7)) * 80u
                        + ((lane >> 3) & 1) * 16u;

    const int KT = K / HK;

    float acc[4][4][4];
    #pragma unroll
    for (int mt = 0; mt < 4; mt++)
        #pragma unroll
        for (int nt = 0; nt < 4; nt++)
            #pragma unroll
            for (int i = 0; i < 4; i++) acc[mt][nt][i] = 0.0f;

    #pragma unroll
    for (int kt = 0; kt < STAGES - 1; kt++) {
        if (kt < KT) {
            unsigned* as = As + (kt % STAGES) * TSZW;
            unsigned* bs = Bs + (kt % STAGES) * TSZW;
            const __half* ap = Ap + (avalid ? kt * HK : 0);
            const __half* bp = Bp + kt * HK;
            cp16(&as[sOff],     ap,     avalid);
            cp16(&as[sOff + 4], ap + 8, avalid);
            cp16(&bs[sOff],     bp,     true);
            cp16(&bs[sOff + 4], bp + 8, true);
        }
        asm volatile("cp.async.commit_group;");
    }

    for (int kt = 0; kt < KT; kt++) {
        asm volatile("cp.async.wait_group %0;" :: "n"(STAGES - 2));
        __syncthreads();

        int kf = kt + STAGES - 1;
        if (kf < KT) {
            unsigned* as = As + (kf % STAGES) * TSZW;
            unsigned* bs = Bs + (kf % STAGES) * TSZW;
            const __half* ap = Ap + (avalid ? kf * HK : 0);
            const __half* bp = Bp + kf * HK;
            cp16(&as[sOff],     ap,     avalid);
            cp16(&as[sOff + 4], ap + 8, avalid);
            cp16(&bs[sOff],     bp,     true);
            cp16(&bs[sOff + 4], bp + 8, true);
        }
        asm volatile("cp.async.commit_group;");

        const uint32_t aBase = sbase + (uint32_t)((kt % STAGES) * TSZW) * 4u + aLds;
        const uint32_t bBase = sbase + (uint32_t)((STAGES + (kt % STAGES)) * TSZW) * 4u + bLds;

        #pragma unroll
        for (int kk = 0; kk < 2; kk++) {
            unsigned af[4][4];
            unsigned bf[4][2];
            #pragma unroll
            for (int mt = 0; mt < 4; mt++)
                ldsm4(af[mt][0], af[mt][1], af[mt][2], af[mt][3],
                      aBase + mt * 1280u + kk * 32u);
            #pragma unroll
            for (int p = 0; p < 2; p++)
                ldsm4(bf[p * 2][0], bf[p * 2][1], bf[p * 2 + 1][0], bf[p * 2 + 1][1],
                      bBase + p * 1280u + kk * 32u);
            #pragma unroll
            for (int mt = 0; mt < 4; mt++)
                #pragma unroll
                for (int nt = 0; nt < 4; nt++)
                    mma_f16(acc[mt][nt], af[mt], bf[nt]);
        }
    }

    // epilogue: whole CTA tile lies in one output region
    const int colBase = bn * GBN;
    const bool rA = colBase < Nsplit;
    const int Wd = rA ? Nsplit : (N - Nsplit);
    const int cb = (rA ? colBase : colBase - Nsplit) + wc;
    const float* bias = rA ? biasA : biasB;

    float bv[4][2];
    #pragma unroll
    for (int nt = 0; nt < 4; nt++) {
        int col = cb + nt * 8 + 2 * tg;
        bv[nt][0] = bias ? bias[col] : 0.0f;
        bv[nt][1] = bias ? bias[col + 1] : 0.0f;
    }

    #pragma unroll
    for (int mt = 0; mt < 4; mt++) {
        #pragma unroll
        for (int i = 0; i < 2; i++) {
            int row = bm * GBM + wr + mt * 16 + g + i * 8;
            if (row >= M) continue;
            size_t rb = (size_t)row * Wd + cb;
            #pragma unroll
            for (int nt = 0; nt < 4; nt++) {
                float2 v;
                v.x = acc[mt][nt][i * 2 + 0] + bv[nt][0];
                v.y = acc[mt][nt][i * 2 + 1] + bv[nt][1];
                if (ACT == 1) {
                    v.x = v.x > 0.f ? v.x : 0.01f * v.x;
                    v.y = v.y > 0.f ? v.y : 0.01f * v.y;
                }
                if (rA) *(float2*)(C + rb + nt * 8 + 2 * tg) = v;
                else    *(__half2*)(C16 + rb + nt * 8 + 2 * tg) = __floats2half2_rn(v.x, v.y);
            }
        }
    }
}

// ---------------- attention scores (fp16 xl) ---------------------------------
__global__ __launch_bounds__(256) void attn_scores_kernel(
    const __half* __restrict__ xl,
    const float* __restrict__ att_src, const float* __restrict__ att_dst,
    float* __restrict__ asrc, float* __restrict__ adst)
{
    int task = blockIdx.x * 8 + (threadIdx.x >> 5);
    if (task >= N_NODES * 4) return;
    int lane = threadIdx.x & 31;
    int n = task >> 2, h = task & 3;

    const __half* xp = xl + (size_t)n * 1024 + h * 256 + lane * 8;
    const float* sp = att_src + h * 256 + lane * 8;
    const float* dp = att_dst + h * 256 + lane * 8;

    uint4 raw = *(const uint4*)xp;
    __half2* hh = (__half2*)&raw;
    float2 p0 = __half22float2(hh[0]);
    float2 p1 = __half22float2(hh[1]);
    float2 p2 = __half22float2(hh[2]);
    float2 p3 = __half22float2(hh[3]);
    float4 a0 = *(const float4*)(sp), a1 = *(const float4*)(sp + 4);
    float4 b0 = *(const float4*)(dp), b1 = *(const float4*)(dp + 4);

    float s1 = p0.x*a0.x + p0.y*a0.y + p1.x*a0.z + p1.y*a0.w
             + p2.x*a1.x + p2.y*a1.y + p3.x*a1.z + p3.y*a1.w;
    float s2 = p0.x*b0.x + p0.y*b0.y + p1.x*b0.z + p1.y*b0.w
             + p2.x*b1.x + p2.y*b1.y + p3.x*b1.z + p3.y*b1.w;

    #pragma unroll
    for (int off = 16; off > 0; off >>= 1) {
        s1 += __shfl_xor_sync(0xffffffffu, s1, off);
        s2 += __shfl_xor_sync(0xffffffffu, s2, off);
    }
    if (lane == 0) {
        asrc[task] = s1;
        adst[task] = s2;
    }
}

// ---------------- layer1 aggregation: unroll-2 fp16 gather -------------------
__global__ __launch_bounds__(256) void gat_aggregate1_kernel(
    const int* __restrict__ off, const int* __restrict__ esrc,
    const __half* __restrict__ xl, const float* __restrict__ asrc,
    const float* __restrict__ adst, const float* __restrict__ h1,
    __half* __restrict__ out_at)
{
    int task = blockIdx.x * 8 + (threadIdx.x >> 5);
    if (task >= N_NODES * 4) return;
    int lane = threadIdx.x & 31;
    int n = task >> 2, h = task & 3;

    const float ad = adst[n * 4 + h];
    const int j0 = off[n], j1 = off[n + 1];

    float uA[8] = {0.f,0.f,0.f,0.f,0.f,0.f,0.f,0.f};
    float uB[8] = {0.f,0.f,0.f,0.f,0.f,0.f,0.f,0.f};
    float ssA = 0.f, ssB = 0.f;

    int j = j0;
    for (; j + 1 < j1; j += 2) {
        int s0 = esrc[j];
        int s1 = esrc[j + 1];
        float a0 = asrc[s0 * 4 + h] + ad;
        float a1 = asrc[s1 * 4 + h] + ad;
        a0 = a0 > 0.f ? a0 : 0.2f * a0;
        a1 = a1 > 0.f ? a1 : 0.2f * a1;
        float w0 = __expf(a0), w1 = __expf(a1);
        ssA += w0; ssB += w1;
        uint4 r0 = *(const uint4*)(xl + (size_t)s0 * 1024 + h * 256 + lane * 8);
        uint4 r1 = *(const uint4*)(xl + (size_t)s1 * 1024 + h * 256 + lane * 8);
        __half2* h0 = (__half2*)&r0;
        __half2* h1p = (__half2*)&r1;
        #pragma unroll
        for (int q = 0; q < 4; q++) {
            float2 p = __half22float2(h0[q]);
            uA[q * 2]     += w0 * p.x;
            uA[q * 2 + 1] += w0 * p.y;
            float2 pq = __half22float2(h1p[q]);
            uB[q * 2]     += w1 * pq.x;
            uB[q * 2 + 1] += w1 * pq.y;
        }
    }
    if (j < j1) {
        int s0 = esrc[j];
        float a0 = asrc[s0 * 4 + h] + ad;
        a0 = a0 > 0.f ? a0 : 0.2f * a0;
        float w0 = __expf(a0);
        ssA += w0;
        uint4 r0 = *(const uint4*)(xl + (size_t)s0 * 1024 + h * 256 + lane * 8);
        __half2* h0 = (__half2*)&r0;
        #pragma unroll
        for (int q = 0; q < 4; q++) {
            float2 p = __half22float2(h0[q]);
            uA[q * 2]     += w0 * p.x;
            uA[q * 2 + 1] += w0 * p.y;
        }
    }

    float inv = 1.0f / (ssA + ssB + 1e-16f);
    size_t base = (size_t)n * 1024 + h * 256 + lane * 8;
    float4 r0 = *(const float4*)(h1 + base);
    float4 r1 = *(const float4*)(h1 + base + 4);
    __half2 o[4];
    o[0] = __floats2half2_rn(r0.x + (uA[0] + uB[0]) * inv, r0.y + (uA[1] + uB[1]) * inv);
    o[1] = __floats2half2_rn(r0.z + (uA[2] + uB[2]) * inv, r0.w + (uA[3] + uB[3]) * inv);
    o[2] = __floats2half2_rn(r1.x + (uA[4] + uB[4]) * inv, r1.y + (uA[5] + uB[5]) * inv);
    o[3] = __floats2half2_rn(r1.z + (uA[6] + uB[6]) * inv, r1.w + (uA[7] + uB[7]) * inv);
    *(uint4*)(out_at + base) = *(uint4*)o;
}

// ---------------- layer2 aggregation: head-mean, prefetched gather -----------
__global__ __launch_bounds__(256) void gat_aggregate2_kernel(
    const int* __restrict__ off, const int* __restrict__ esrc,
    const __half* __restrict__ xl, const float* __restrict__ asrc,
    const float* __restrict__ adst, const float* __restrict__ h2,
    __half* __restrict__ out_at)
{
    int n = blockIdx.x * 8 + (threadIdx.x >> 5);
    if (n >= N_NODES) return;
    int lane = threadIdx.x & 31;

    float4 ad = *(const float4*)(adst + n * 4);
    const int j0 = off[n], j1 = off[n + 1];

    float u[4][8];
    #pragma unroll
    for (int h = 0; h < 4; h++)
        #pragma unroll
        for (int q = 0; q < 8; q++) u[h][q] = 0.f;
    float4 ssum = make_float4(0.f, 0.f, 0.f, 0.f);

    int sNext = (j0 < j1) ? esrc[j0] : 0;
    float4 asNext = (j0 < j1) ? *(const float4*)(asrc + sNext * 4)
                              : make_float4(0.f, 0.f, 0.f, 0.f);

    for (int j = j0; j < j1; j++) {
        int s = sNext;
        float4 as = asNext;
        if (j + 1 < j1) {
            sNext = esrc[j + 1];
            asNext = *(const float4*)(asrc + sNext * 4);
        }
        float4 e;
        e.x = as.x + ad.x; e.x = e.x > 0.f ? e.x : 0.2f * e.x;
        e.y = as.y + ad.y; e.y = e.y > 0.f ? e.y : 0.2f * e.y;
        e.z = as.z + ad.z; e.z = e.z > 0.f ? e.z : 0.2f * e.z;
        e.w = as.w + ad.w; e.w = e.w > 0.f ? e.w : 0.2f * e.w;
        float w[4];
        w[0] = __expf(e.x); w[1] = __expf(e.y); w[2] = __expf(e.z); w[3] = __expf(e.w);
        ssum.x += w[0]; ssum.y += w[1]; ssum.z += w[2]; ssum.w += w[3];

        const __half* sp = xl + (size_t)s * 1024 + lane * 8;
        #pragma unroll
        for (int h = 0; h < 4; h++) {
            uint4 raw = *(const uint4*)(sp + h * 256);
            __half2* hh = (__half2*)&raw;
            float2 p0 = __half22float2(hh[0]);
            float2 p1 = __half22float2(hh[1]);
            float2 p2 = __half22float2(hh[2]);
            float2 p3 = __half22float2(hh[3]);
            u[h][0] += w[h] * p0.x; u[h][1] += w[h] * p0.y;
            u[h][2] += w[h] * p1.x; u[h][3] += w[h] * p1.y;
            u[h][4] += w[h] * p2.x; u[h][5] += w[h] * p2.y;
            u[h][6] += w[h] * p3.x; u[h][7] += w[h] * p3.y;
        }
    }

    float i0 = 0.25f / (ssum.x + 1e-16f);
    float i1 = 0.25f / (ssum.y + 1e-16f);
    float i2 = 0.25f / (ssum.z + 1e-16f);
    float i3 = 0.25f / (ssum.w + 1e-16f);

    size_t base = (size_t)n * 256 + lane * 8;
    float4 r0 = *(const float4*)(h2 + base);
    float4 r1 = *(const float4*)(h2 + base + 4);
    float o[8];
    o[0] = r0.x + i0*u[0][0] + i1*u[1][0] + i2*u[2][0] + i3*u[3][0];
    o[1] = r0.y + i0*u[0][1] + i1*u[1][1] + i2*u[2][1] + i3*u[3][1];
    o[2] = r0.z + i0*u[0][2] + i1*u[1][2] + i2*u[2][2] + i3*u[3][2];
    o[3] = r0.w + i0*u[0][3] + i1*u[1][3] + i2*u[2][3] + i3*u[3][3];
    o[4] = r1.x + i0*u[0][4] + i1*u[1][4] + i2*u[2][4] + i3*u[3][4];
    o[5] = r1.y + i0*u[0][5] + i1*u[1][5] + i2*u[2][5] + i3*u[3][5];
    o[6] = r1.z + i0*u[0][6] + i1*u[1][6] + i2*u[2][6] + i3*u[3][6];
    o[7] = r1.w + i0*u[0][7] + i1*u[1][7] + i2*u[2][7] + i3*u[3][7];
    __half2 ho[4];
    ho[0] = __floats2half2_rn(o[0], o[1]);
    ho[1] = __floats2half2_rn(o[2], o[3]);
    ho[2] = __floats2half2_rn(o[4], o[5]);
    ho[3] = __floats2half2_rn(o[6], o[7]);
    *(uint4*)(out_at + base) = *(uint4*)ho;
}

// ---------------- output heads (fp16 input) ----------------------------------
__global__ __launch_bounds__(256) void heads_kernel(
    const __half* __restrict__ fc,
    const float* __restrict__ Wb, const float* __restrict__ bb,
    const float* __restrict__ Ws, const float* __restrict__ bs,
    float* __restrict__ out)
{
    int n = blockIdx.x * 8 + (threadIdx.x >> 5);
    if (n >= N_NODES) return;
    int lane = threadIdx.x & 31;

    float acc[7] = {0.f, 0.f, 0.f, 0.f, 0.f, 0.f, 0.f};
    #pragma unroll
    for (int i = 0; i < 8; i++) {
        int k = i * 32 + lane;
        float v = __half2float(fc[(size_t)n * 256 + k]);
        acc[0] += v * Wb[k * 2 + 0];
        acc[1] += v * Wb[k * 2 + 1];
        #pragma unroll
        for (int j = 0; j < 5; j++) acc[2 + j] += v * Ws[k * 5 + j];
    }
    #pragma unroll
    for (int off = 16; off > 0; off >>= 1) {
        #pragma unroll
        for (int j = 0; j < 7; j++) acc[j] += __shfl_xor_sync(0xffffffffu, acc[j], off);
    }
    if (lane == 0) {
        out[(size_t)n * 2 + 0] = acc[0] + bb[0];
        out[(size_t)n * 2 + 1] = acc[1] + bb[1];
        float* sev = out + (size_t)N_NODES * 2 + (size_t)n * 5;
        #pragma unroll
        for (int j = 0; j < 5; j++) sev[j] = acc[2 + j] + bs[j];
    }
}

// ---------------- launch ------------------------------------------------------
static inline void cvt(const float* in, __half* out, int n, cudaStream_t st = 0) {
    cvt_fp16_kernel<<<(n / 8 + 255) / 256, 256, 0, st>>>(in, out, n);
}
static inline void cvtT(const float* W, __half* out, int K, int N, cudaStream_t st = 0) {
    dim3 grid(N / 32, K / 32);
    cvt_fp16_transpose_kernel<<<grid, dim3(32, 8), 0, st>>>(W, out, K, N);
}

extern "C" void kernel_launch(void* const* d_in, const int* in_sizes, int n_in,
                              void* d_out, int out_size)
{
    const float* x        = (const float*)d_in[0];
    const int*   ei       = (const int*)d_in[1];
    const float* W1       = (const float*)d_in[2];
    const float* att_src1 = (const float*)d_in[3];
    const float* att_dst1 = (const float*)d_in[4];
    const float* Wres1    = (const float*)d_in[5];
    const float* b1       = (const float*)d_in[6];
    const float* W2       = (const float*)d_in[7];
    const float* att_src2 = (const float*)d_in[8];
    const float* att_dst2 = (const float*)d_in[9];
    const float* Wres2    = (const float*)d_in[10];
    const float* b2       = (const float*)d_in[11];
    const float* Wfc      = (const float*)d_in[12];
    const float* bfc      = (const float*)d_in[13];
    const float* Wb       = (const float*)d_in[14];
    const float* bb       = (const float*)d_in[15];
    const float* Ws       = (const float*)d_in[16];
    const float* bs       = (const float*)d_in[17];
    float* out = (float*)d_out;

    const int* src = ei;
    const int* dst = ei + N_EDGES;

    float *h1, *h2, *asrc, *adst;
    __half *xl16, *at, *wt, *fc1h, *fc2h;
    int *deg, *off, *cur, *esrc;
    cudaGetSymbolAddress((void**)&xl16, g_xl16);
    cudaGetSymbolAddress((void**)&h1,   g_h1);
    cudaGetSymbolAddress((void**)&h2,   g_h2);
    cudaGetSymbolAddress((void**)&fc1h, g_fc1h);
    cudaGetSymbolAddress((void**)&fc2h, g_fc2h);
    cudaGetSymbolAddress((void**)&at,   g_at);
    cudaGetSymbolAddress((void**)&wt,   g_wt);
    cudaGetSymbolAddress((void**)&asrc, g_asrc);
    cudaGetSymbolAddress((void**)&adst, g_adst);
    cudaGetSymbolAddress((void**)&deg,  g_deg);
    cudaGetSymbolAddress((void**)&off,  g_off);
    cudaGetSymbolAddress((void**)&cur,  g_cur);
    cudaGetSymbolAddress((void**)&esrc, g_esrc);

    static bool init_done = false;
    static cudaStream_t s1;
    static cudaEvent_t ev0, evCsr, evGemm1, evW2, evGemm2, evWfc;
    if (!init_done) {
        cudaFuncSetAttribute(mma_gemm_kernel<0>,
                             cudaFuncAttributeMaxDynamicSharedMemorySize, GEMM_SMEM);
        cudaFuncSetAttribute(mma_gemm_kernel<1>,
                             cudaFuncAttributeMaxDynamicSharedMemorySize, GEMM_SMEM);
        cudaStreamCreateWithFlags(&s1, cudaStreamNonBlocking);
        cudaEventCreateWithFlags(&ev0,    cudaEventDisableTiming);
        cudaEventCreateWithFlags(&evCsr,  cudaEventDisableTiming);
        cudaEventCreateWithFlags(&evGemm1, cudaEventDisableTiming);
        cudaEventCreateWithFlags(&evW2,   cudaEventDisableTiming);
        cudaEventCreateWithFlags(&evGemm2, cudaEventDisableTiming);
        cudaEventCreateWithFlags(&evWfc,  cudaEventDisableTiming);
        init_done = true;
    }

    const int mRows = (N_NODES + GBM - 1) / GBM;
    const int attnBlocks = (N_NODES * 4 + 7) / 8;
    const int nodeBlocks = (N_NODES + 7) / 8;
    const int edgeBlocks = (N_EDGES + 255) / 256;

    // fork side stream from main
    cudaEventRecord(ev0, 0);
    cudaStreamWaitEvent(s1, ev0, 0);

    // ---- side stream: CSR build (independent of GEMM chain) ----
    zero_deg_kernel<<<(N_NODES + 255) / 256, 256, 0, s1>>>(deg);
    hist_kernel<<<edgeBlocks, 256, 0, s1>>>(dst, deg);
    scan_kernel<<<1, 256, 0, s1>>>(deg, off, cur);
    scatter_kernel<<<edgeBlocks, 256, 0, s1>>>(src, dst, cur, esrc);
    cudaEventRecord(evCsr, s1);

    // ---- main: operand prep + fused layer1 GEMM ----
    cvt(x, at, N_NODES * 768);
    cvtT(Wres1, wt, 768, 1024);
    cvtT(W1, wt + (size_t)1024 * 768, 768, 1024);
    {
        dim3 grid(2048 / GBN, mRows);
        mma_gemm_kernel<0><<<grid, 256, GEMM_SMEM>>>(at, wt, b1, nullptr, h1, xl16,
                                                     N_NODES, 2048, 768, 1024);
    }
    cudaEventRecord(evGemm1, 0);

    // ---- side stream: layer2 weight conversions (after GEMM1 done with wt) ----
    cudaStreamWaitEvent(s1, evGemm1, 0);
    cvtT(Wres2, wt, 1024, 256, s1);
    cvtT(W2, wt + (size_t)256 * 1024, 1024, 1024, s1);
    cudaEventRecord(evW2, s1);

    // ---- main: layer 1 aggregation -> fp16 'at' ----
    attn_scores_kernel<<<attnBlocks, 256>>>(xl16, att_src1, att_dst1, asrc, adst);
    cudaStreamWaitEvent(0, evCsr, 0);
    gat_aggregate1_kernel<<<attnBlocks, 256>>>(off, esrc, xl16, asrc, adst, h1, at);

    // ---- main: fused layer2 GEMM (needs wt from side stream) ----
    cudaStreamWaitEvent(0, evW2, 0);
    {
        dim3 grid(1280 / GBN, mRows);
        mma_gemm_kernel<0><<<grid, 256, GEMM_SMEM>>>(at, wt, b2, nullptr, h2, xl16,
                                                     N_NODES, 1280, 1024, 256);
    }
    cudaEventRecord(evGemm2, 0);

    // ---- side stream: fc weight conversion ----
    cudaStreamWaitEvent(s1, evGemm2, 0);
    cvtT(Wfc, wt, 256, 256, s1);
    cudaEventRecord(evWfc, s1);

    // ---- main: layer 2 aggregation ----
    attn_scores_kernel<<<attnBlocks, 256>>>(xl16, att_src2, att_dst2, asrc, adst);
    gat_aggregate2_kernel<<<nodeBlocks, 256>>>(off, esrc, xl16, asrc, adst, h2, at);

    // ---- main: shared FC twice (both fp16 out) ----
    cudaStreamWaitEvent(0, evWfc, 0);
    {
        dim3 grid(256 / GBN, mRows);
        mma_gemm_kernel<1><<<grid, 256, GEMM_SMEM>>>(at, wt, nullptr, bfc, nullptr, fc1h,
                                                     N_NODES, 256, 256, 0);
        mma_gemm_kernel<0><<<grid, 256, GEMM_SMEM>>>(fc1h, wt, nullptr, bfc, nullptr, fc2h,
                                                     N_NODES, 256, 256, 0);
    }

    // ---- heads ----
    heads_kernel<<<nodeBlocks, 256>>>(fc2h, Wb, bb, Ws, bs, out);
}

// round 16
// speedup vs baseline: 1.2074x; 1.0063x over previous
#include <cuda_runtime.h>
#include <cuda_fp16.h>
#include <cstdint>

#define N_NODES 20000
#define N_EDGES 320000

// ---------------- scratch (device globals; no allocation allowed) ----------
__device__ __half g_xl16[N_NODES * 1024];  // fp16 per-head features (gather source)
__device__ __half g_res16[N_NODES * 1024]; // fp16 layer1 residual -> layer2 input
__device__ float  g_h2[N_NODES * 256];     // layer2 residual GEMM output (read once)
__device__ __half g_fc1h[N_NODES * 256];   // fp16 fc1 output
__device__ float  g_fc2[N_NODES * 256];    // fp32 fc2 output
__device__ __half g_at[N_NODES * 1024];    // fp16 A operand (x for layer1; h2agg for fc)
__device__ __half g_wt[2048 * 1024];       // fp16 transposed packed weights [N,K]
__device__ float  g_asrc[N_NODES * 4];
__device__ float  g_adst[N_NODES * 4];
__device__ int    g_deg[N_NODES];
__device__ int    g_off[N_NODES + 1];
__device__ int    g_cur[N_NODES];
__device__ int    g_esrc[N_EDGES];         // src node of each edge, grouped by dst

// ---------------- helpers ---------------------------------------------------
__device__ __forceinline__ void mma_f16(float* d, const unsigned* a, const unsigned* b) {
    asm volatile(
        "mma.sync.aligned.m16n8k16.row.col.f32.f16.f16.f32 "
        "{%0,%1,%2,%3}, {%4,%5,%6,%7}, {%8,%9}, {%0,%1,%2,%3};"
        : "+f"(d[0]), "+f"(d[1]), "+f"(d[2]), "+f"(d[3])
        : "r"(a[0]), "r"(a[1]), "r"(a[2]), "r"(a[3]), "r"(b[0]), "r"(b[1]));
}

__device__ __forceinline__ void ldsm4(unsigned& r0, unsigned& r1, unsigned& r2, unsigned& r3,
                                      uint32_t addr) {
    asm volatile("ldmatrix.sync.aligned.m8n8.x4.shared.b16 {%0,%1,%2,%3}, [%4];"
                 : "=r"(r0), "=r"(r1), "=r"(r2), "=r"(r3) : "r"(addr));
}

__device__ __forceinline__ void cp16(void* smem, const void* gmem, bool pred) {
    unsigned sa = (unsigned)__cvta_generic_to_shared(smem);
    int sz = pred ? 16 : 0;
    asm volatile("cp.async.cg.shared.global [%0], [%1], 16, %2;"
                 :: "r"(sa), "l"(gmem), "r"(sz));
}

// ---------------- fp16 conversion passes -------------------------------------
__global__ void cvt_fp16_kernel(const float* __restrict__ in, __half* __restrict__ out, int n) {
    int i = (blockIdx.x * blockDim.x + threadIdx.x) * 8;
    if (i >= n) return;
    float4 v0 = *(const float4*)(in + i);
    float4 v1 = *(const float4*)(in + i + 4);
    __half2 h[4];
    h[0] = __floats2half2_rn(v0.x, v0.y);
    h[1] = __floats2half2_rn(v0.z, v0.w);
    h[2] = __floats2half2_rn(v1.x, v1.y);
    h[3] = __floats2half2_rn(v1.z, v1.w);
    *(uint4*)(out + i) = *(uint4*)h;
}

// weights: W[K,N] fp32 -> out[N,K] fp16 (transposed). K,N multiples of 32.
__global__ void cvt_fp16_transpose_kernel(const float* __restrict__ in, __half* __restrict__ out,
                                          int K, int N) {
    __shared__ float t[32][33];
    int k0 = blockIdx.y * 32, n0 = blockIdx.x * 32;
    int tx = threadIdx.x, ty = threadIdx.y;  // 32 x 8
    #pragma unroll
    for (int j = 0; j < 32; j += 8)
        t[ty + j][tx] = in[(size_t)(k0 + ty + j) * N + n0 + tx];
    __syncthreads();
    #pragma unroll
    for (int j = 0; j < 32; j += 8)
        out[(size_t)(n0 + ty + j) * K + k0 + tx] = __float2half_rn(t[tx][ty + j]);
}

// ---------------- CSR build ---------------------------------------------------
__global__ void zero_deg_kernel(int* __restrict__ deg) {
    int i = blockIdx.x * blockDim.x + threadIdx.x;
    if (i < N_NODES) deg[i] = 0;
}

__global__ void hist_kernel(const int* __restrict__ dst, int* __restrict__ deg) {
    int e = blockIdx.x * blockDim.x + threadIdx.x;
    if (e < N_EDGES) atomicAdd(&deg[dst[e]], 1);
}

__global__ __launch_bounds__(256) void scan_kernel(
    const int* __restrict__ deg, int* __restrict__ off, int* __restrict__ cur)
{
    __shared__ int partial[256];
    const int tid = threadIdx.x;
    const int CH = (N_NODES + 255) / 256;
    const int base = tid * CH;

    int s = 0;
    for (int j = 0; j < CH; j++) {
        int i = base + j;
        if (i < N_NODES) s += deg[i];
    }
    partial[tid] = s;
    __syncthreads();
    for (int o = 1; o < 256; o <<= 1) {
        int v = (tid >= o) ? partial[tid - o] : 0;
        __syncthreads();
        partial[tid] += v;
        __syncthreads();
    }
    int run = partial[tid] - s;
    for (int j = 0; j < CH; j++) {
        int i = base + j;
        if (i < N_NODES) {
            off[i] = run;
            cur[i] = run;
            run += deg[i];
        }
    }
    if (tid == 255) off[N_NODES] = run;
}

__global__ void scatter_kernel(const int* __restrict__ src, const int* __restrict__ dst,
                               int* __restrict__ cur, int* __restrict__ esrc) {
    int e = blockIdx.x * blockDim.x + threadIdx.x;
    if (e >= N_EDGES) return;
    int pos = atomicAdd(&cur[dst[e]], 1);
    esrc[pos] = src[e];
}

// ---------------- fp16 tensor-core GEMM, cp.async 4-stage, single-sync -------
// C_all[M,N] = A[M,K] @ Bt[N,K]^T. Split output:
//   region A: columns [0,Nsplit), bias biasA; fp32 to C if C!=null else fp16 to CA16
//   region B: columns [Nsplit,N), bias biasB; fp16 to C16
// Row strides: region A -> Nsplit, region B -> N-Nsplit. Nsplit % 128 == 0.
// CTA tile 128x128, K-tile 32 halves (80B row pitch, ldmatrix conflict-free),
// 8 warps (2x4) 64x32, mma m16n8k16, single sync per k-tile.
// Requires N % 128 == 0, K % 32 == 0; M guarded.
#define GBM 128
#define GBN 128
#define HK 32
#define ROWW 20
#define TSZW (128 * ROWW)
#define STAGES 4
#define GEMM_SMEM (STAGES * 2 * TSZW * 4)   // 81920 bytes

template <int ACT>  // 0: none, 1: leaky_relu(0.01)
__global__ __launch_bounds__(256, 2) void mma_gemm_kernel(
    const __half* __restrict__ A, const __half* __restrict__ Bt,
    const float* __restrict__ biasA, const float* __restrict__ biasB,
    float* __restrict__ C, __half* __restrict__ CA16, __half* __restrict__ C16,
    int M, int N, int K, int Nsplit)
{
    extern __shared__ unsigned smem[];
    unsigned* As = smem;
    unsigned* Bs = smem + STAGES * TSZW;

    const int tid = threadIdx.x;
    const int warp = tid >> 5, lane = tid & 31;
    const int g = lane >> 2, tg = lane & 3;
    const int wr = (warp >> 2) * 64;
    const int wc = (warp & 3) * 32;

    const int bm = blockIdx.y, bn = blockIdx.x;

    const int rowS = tid >> 1;
    const int rowA = bm * GBM + rowS;
    const bool avalid = rowA < M;
    const __half* Ap = avalid ? (A + (size_t)rowA * K + (tid & 1) * 16) : A;
    const __half* Bp = Bt + (size_t)(bn * GBN + rowS) * K + (tid & 1) * 16;
    const int sOff = rowS * ROWW + (tid & 1) * 8;

    const uint32_t sbase = (uint32_t)__cvta_generic_to_shared(smem);
    const uint32_t aLds = (uint32_t)(wr + (lane & 15)) * 80u + ((lane >> 4) & 1) * 16u;
    const uint32_t bLds = (uint32_t)(wc + ((lane >> 4) & 1) * 8 + (lane & 7)) * 80u
                        + ((lane >> 3) & 1) * 16u;

    const int KT = K / HK;

    float acc[4][4][4];
    #pragma unroll
    for (int mt = 0; mt < 4; mt++)
        #pragma unroll
        for (int nt = 0; nt < 4; nt++)
            #pragma unroll
            for (int i = 0; i < 4; i++) acc[mt][nt][i] = 0.0f;

    #pragma unroll
    for (int kt = 0; kt < STAGES - 1; kt++) {
        if (kt < KT) {
            unsigned* as = As + (kt % STAGES) * TSZW;
            unsigned* bs = Bs + (kt % STAGES) * TSZW;
            const __half* ap = Ap + (avalid ? kt * HK : 0);
            const __half* bp = Bp + kt * HK;
            cp16(&as[sOff],     ap,     avalid);
            cp16(&as[sOff + 4], ap + 8, avalid);
            cp16(&bs[sOff],     bp,     true);
            cp16(&bs[sOff + 4], bp + 8, true);
        }
        asm volatile("cp.async.commit_group;");
    }

    for (int kt = 0; kt < KT; kt++) {
        asm volatile("cp.async.wait_group %0;" :: "n"(STAGES - 2));
        __syncthreads();

        int kf = kt + STAGES - 1;
        if (kf < KT) {
            unsigned* as = As + (kf % STAGES) * TSZW;
            unsigned* bs = Bs + (kf % STAGES) * TSZW;
            const __half* ap = Ap + (avalid ? kf * HK : 0);
            const __half* bp = Bp + kf * HK;
            cp16(&as[sOff],     ap,     avalid);
            cp16(&as[sOff + 4], ap + 8, avalid);
            cp16(&bs[sOff],     bp,     true);
            cp16(&bs[sOff + 4], bp + 8, true);
        }
        asm volatile("cp.async.commit_group;");

        const uint32_t aBase = sbase + (uint32_t)((kt % STAGES) * TSZW) * 4u + aLds;
        const uint32_t bBase = sbase + (uint32_t)((STAGES + (kt % STAGES)) * TSZW) * 4u + bLds;

        #pragma unroll
        for (int kk = 0; kk < 2; kk++) {
            unsigned af[4][4];
            unsigned bf[4][2];
            #pragma unroll
            for (int mt = 0; mt < 4; mt++)
                ldsm4(af[mt][0], af[mt][1], af[mt][2], af[mt][3],
                      aBase + mt * 1280u + kk * 32u);
            #pragma unroll
            for (int p = 0; p < 2; p++)
                ldsm4(bf[p * 2][0], bf[p * 2][1], bf[p * 2 + 1][0], bf[p * 2 + 1][1],
                      bBase + p * 1280u + kk * 32u);
            #pragma unroll
            for (int mt = 0; mt < 4; mt++)
                #pragma unroll
                for (int nt = 0; nt < 4; nt++)
                    mma_f16(acc[mt][nt], af[mt], bf[nt]);
        }
    }

    // epilogue: whole CTA tile lies in one output region
    const int colBase = bn * GBN;
    const bool rA = colBase < Nsplit;
    const int Wd = rA ? Nsplit : (N - Nsplit);
    const int cb = (rA ? colBase : colBase - Nsplit) + wc;
    const float* bias = rA ? biasA : biasB;

    float bv[4][2];
    #pragma unroll
    for (int nt = 0; nt < 4; nt++) {
        int col = cb + nt * 8 + 2 * tg;
        bv[nt][0] = bias ? bias[col] : 0.0f;
        bv[nt][1] = bias ? bias[col + 1] : 0.0f;
    }

    #pragma unroll
    for (int mt = 0; mt < 4; mt++) {
        #pragma unroll
        for (int i = 0; i < 2; i++) {
            int row = bm * GBM + wr + mt * 16 + g + i * 8;
            if (row >= M) continue;
            size_t rb = (size_t)row * Wd + cb;
            #pragma unroll
            for (int nt = 0; nt < 4; nt++) {
                float2 v;
                v.x = acc[mt][nt][i * 2 + 0] + bv[nt][0];
                v.y = acc[mt][nt][i * 2 + 1] + bv[nt][1];
                if (ACT == 1) {
                    v.x = v.x > 0.f ? v.x : 0.01f * v.x;
                    v.y = v.y > 0.f ? v.y : 0.01f * v.y;
                }
                if (rA) {
                    if (C) *(float2*)(C + rb + nt * 8 + 2 * tg) = v;
                    else   *(__half2*)(CA16 + rb + nt * 8 + 2 * tg) = __floats2half2_rn(v.x, v.y);
                } else {
                    *(__half2*)(C16 + rb + nt * 8 + 2 * tg) = __floats2half2_rn(v.x, v.y);
                }
            }
        }
    }
}

// ---------------- attention scores (fp16 xl) ---------------------------------
__global__ __launch_bounds__(256) void attn_scores_kernel(
    const __half* __restrict__ xl,
    const float* __restrict__ att_src, const float* __restrict__ att_dst,
    float* __restrict__ asrc, float* __restrict__ adst)
{
    int task = blockIdx.x * 8 + (threadIdx.x >> 5);
    if (task >= N_NODES * 4) return;
    int lane = threadIdx.x & 31;
    int n = task >> 2, h = task & 3;

    const __half* xp = xl + (size_t)n * 1024 + h * 256 + lane * 8;
    const float* sp = att_src + h * 256 + lane * 8;
    const float* dp = att_dst + h * 256 + lane * 8;

    uint4 raw = *(const uint4*)xp;
    __half2* hh = (__half2*)&raw;
    float2 p0 = __half22float2(hh[0]);
    float2 p1 = __half22float2(hh[1]);
    float2 p2 = __half22float2(hh[2]);
    float2 p3 = __half22float2(hh[3]);
    float4 a0 = *(const float4*)(sp), a1 = *(const float4*)(sp + 4);
    float4 b0 = *(const float4*)(dp), b1 = *(const float4*)(dp + 4);

    float s1 = p0.x*a0.x + p0.y*a0.y + p1.x*a0.z + p1.y*a0.w
             + p2.x*a1.x + p2.y*a1.y + p3.x*a1.z + p3.y*a1.w;
    float s2 = p0.x*b0.x + p0.y*b0.y + p1.x*b0.z + p1.y*b0.w
             + p2.x*b1.x + p2.y*b1.y + p3.x*b1.z + p3.y*b1.w;

    #pragma unroll
    for (int off = 16; off > 0; off >>= 1) {
        s1 += __shfl_xor_sync(0xffffffffu, s1, off);
        s2 += __shfl_xor_sync(0xffffffffu, s2, off);
    }
    if (lane == 0) {
        asrc[task] = s1;
        adst[task] = s2;
    }
}

// ---------------- layer1 aggregation: unroll-2 fp16 gather, in-place res -----
// 'res' holds the fp16 residual (x@Wres1+b1); add softmax agg in place.
__global__ __launch_bounds__(256) void gat_aggregate1_kernel(
    const int* __restrict__ off, const int* __restrict__ esrc,
    const __half* __restrict__ xl, const float* __restrict__ asrc,
    const float* __restrict__ adst, __half* __restrict__ res)
{
    int task = blockIdx.x * 8 + (threadIdx.x >> 5);
    if (task >= N_NODES * 4) return;
    int lane = threadIdx.x & 31;
    int n = task >> 2, h = task & 3;

    const float ad = adst[n * 4 + h];
    const int j0 = off[n], j1 = off[n + 1];

    float uA[8] = {0.f,0.f,0.f,0.f,0.f,0.f,0.f,0.f};
    float uB[8] = {0.f,0.f,0.f,0.f,0.f,0.f,0.f,0.f};
    float ssA = 0.f, ssB = 0.f;

    int j = j0;
    for (; j + 1 < j1; j += 2) {
        int s0 = esrc[j];
        int s1 = esrc[j + 1];
        float a0 = asrc[s0 * 4 + h] + ad;
        float a1 = asrc[s1 * 4 + h] + ad;
        a0 = a0 > 0.f ? a0 : 0.2f * a0;
        a1 = a1 > 0.f ? a1 : 0.2f * a1;
        float w0 = __expf(a0), w1 = __expf(a1);
        ssA += w0; ssB += w1;
        uint4 r0 = *(const uint4*)(xl + (size_t)s0 * 1024 + h * 256 + lane * 8);
        uint4 r1 = *(const uint4*)(xl + (size_t)s1 * 1024 + h * 256 + lane * 8);
        __half2* h0 = (__half2*)&r0;
        __half2* h1p = (__half2*)&r1;
        #pragma unroll
        for (int q = 0; q < 4; q++) {
            float2 p = __half22float2(h0[q]);
            uA[q * 2]     += w0 * p.x;
            uA[q * 2 + 1] += w0 * p.y;
            float2 pq = __half22float2(h1p[q]);
            uB[q * 2]     += w1 * pq.x;
            uB[q * 2 + 1] += w1 * pq.y;
        }
    }
    if (j < j1) {
        int s0 = esrc[j];
        float a0 = asrc[s0 * 4 + h] + ad;
        a0 = a0 > 0.f ? a0 : 0.2f * a0;
        float w0 = __expf(a0);
        ssA += w0;
        uint4 r0 = *(const uint4*)(xl + (size_t)s0 * 1024 + h * 256 + lane * 8);
        __half2* h0 = (__half2*)&r0;
        #pragma unroll
        for (int q = 0; q < 4; q++) {
            float2 p = __half22float2(h0[q]);
            uA[q * 2]     += w0 * p.x;
            uA[q * 2 + 1] += w0 * p.y;
        }
    }

    float inv = 1.0f / (ssA + ssB + 1e-16f);
    size_t base = (size_t)n * 1024 + h * 256 + lane * 8;
    uint4 rr = *(const uint4*)(res + base);
    __half2* rh = (__half2*)&rr;
    float2 q0 = __half22float2(rh[0]);
    float2 q1 = __half22float2(rh[1]);
    float2 q2 = __half22float2(rh[2]);
    float2 q3 = __half22float2(rh[3]);
    __half2 o[4];
    o[0] = __floats2half2_rn(q0.x + (uA[0] + uB[0]) * inv, q0.y + (uA[1] + uB[1]) * inv);
    o[1] = __floats2half2_rn(q1.x + (uA[2] + uB[2]) * inv, q1.y + (uA[3] + uB[3]) * inv);
    o[2] = __floats2half2_rn(q2.x + (uA[4] + uB[4]) * inv, q2.y + (uA[5] + uB[5]) * inv);
    o[3] = __floats2half2_rn(q3.x + (uA[6] + uB[6]) * inv, q3.y + (uA[7] + uB[7]) * inv);
    *(uint4*)(res + base) = *(uint4*)o;
}

// ---------------- layer2 aggregation: head-mean, prefetched gather -----------
__global__ __launch_bounds__(256) void gat_aggregate2_kernel(
    const int* __restrict__ off, const int* __restrict__ esrc,
    const __half* __restrict__ xl, const float* __restrict__ asrc,
    const float* __restrict__ adst, const float* __restrict__ h2,
    __half* __restrict__ out_at)
{
    int n = blockIdx.x * 8 + (threadIdx.x >> 5);
    if (n >= N_NODES) return;
    int lane = threadIdx.x & 31;

    float4 ad = *(const float4*)(adst + n * 4);
    const int j0 = off[n], j1 = off[n + 1];

    float u[4][8];
    #pragma unroll
    for (int h = 0; h < 4; h++)
        #pragma unroll
        for (int q = 0; q < 8; q++) u[h][q] = 0.f;
    float4 ssum = make_float4(0.f, 0.f, 0.f, 0.f);

    int sNext = (j0 < j1) ? esrc[j0] : 0;
    float4 asNext = (j0 < j1) ? *(const float4*)(asrc + sNext * 4)
                              : make_float4(0.f, 0.f, 0.f, 0.f);

    for (int j = j0; j < j1; j++) {
        int s = sNext;
        float4 as = asNext;
        if (j + 1 < j1) {
            sNext = esrc[j + 1];
            asNext = *(const float4*)(asrc + sNext * 4);
        }
        float4 e;
        e.x = as.x + ad.x; e.x = e.x > 0.f ? e.x : 0.2f * e.x;
        e.y = as.y + ad.y; e.y = e.y > 0.f ? e.y : 0.2f * e.y;
        e.z = as.z + ad.z; e.z = e.z > 0.f ? e.z : 0.2f * e.z;
        e.w = as.w + ad.w; e.w = e.w > 0.f ? e.w : 0.2f * e.w;
        float w[4];
        w[0] = __expf(e.x); w[1] = __expf(e.y); w[2] = __expf(e.z); w[3] = __expf(e.w);
        ssum.x += w[0]; ssum.y += w[1]; ssum.z += w[2]; ssum.w += w[3];

        const __half* sp = xl + (size_t)s * 1024 + lane * 8;
        #pragma unroll
        for (int h = 0; h < 4; h++) {
            uint4 raw = *(const uint4*)(sp + h * 256);
            __half2* hh = (__half2*)&raw;
            float2 p0 = __half22float2(hh[0]);
            float2 p1 = __half22float2(hh[1]);
            float2 p2 = __half22float2(hh[2]);
            float2 p3 = __half22float2(hh[3]);
            u[h][0] += w[h] * p0.x; u[h][1] += w[h] * p0.y;
            u[h][2] += w[h] * p1.x; u[h][3] += w[h] * p1.y;
            u[h][4] += w[h] * p2.x; u[h][5] += w[h] * p2.y;
            u[h][6] += w[h] * p3.x; u[h][7] += w[h] * p3.y;
        }
    }

    float i0 = 0.25f / (ssum.x + 1e-16f);
    float i1 = 0.25f / (ssum.y + 1e-16f);
    float i2 = 0.25f / (ssum.z + 1e-16f);
    float i3 = 0.25f / (ssum.w + 1e-16f);

    size_t base = (size_t)n * 256 + lane * 8;
    float4 r0 = *(const float4*)(h2 + base);
    float4 r1 = *(const float4*)(h2 + base + 4);
    float o[8];
    o[0] = r0.x + i0*u[0][0] + i1*u[1][0] + i2*u[2][0] + i3*u[3][0];
    o[1] = r0.y + i0*u[0][1] + i1*u[1][1] + i2*u[2][1] + i3*u[3][1];
    o[2] = r0.z + i0*u[0][2] + i1*u[1][2] + i2*u[2][2] + i3*u[3][2];
    o[3] = r0.w + i0*u[0][3] + i1*u[1][3] + i2*u[2][3] + i3*u[3][3];
    o[4] = r1.x + i0*u[0][4] + i1*u[1][4] + i2*u[2][4] + i3*u[3][4];
    o[5] = r1.y + i0*u[0][5] + i1*u[1][5] + i2*u[2][5] + i3*u[3][5];
    o[6] = r1.z + i0*u[0][6] + i1*u[1][6] + i2*u[2][6] + i3*u[3][6];
    o[7] = r1.w + i0*u[0][7] + i1*u[1][7] + i2*u[2][7] + i3*u[3][7];
    __half2 ho[4];
    ho[0] = __floats2half2_rn(o[0], o[1]);
    ho[1] = __floats2half2_rn(o[2], o[3]);
    ho[2] = __floats2half2_rn(o[4], o[5]);
    ho[3] = __floats2half2_rn(o[6], o[7]);
    *(uint4*)(out_at + base) = *(uint4*)ho;
}

// ---------------- output heads (fp32 input) ----------------------------------
__global__ __launch_bounds__(256) void heads_kernel(
    const float* __restrict__ fc,
    const float* __restrict__ Wb, const float* __restrict__ bb,
    const float* __restrict__ Ws, const float* __restrict__ bs,
    float* __restrict__ out)
{
    int n = blockIdx.x * 8 + (threadIdx.x >> 5);
    if (n >= N_NODES) return;
    int lane = threadIdx.x & 31;

    float acc[7] = {0.f, 0.f, 0.f, 0.f, 0.f, 0.f, 0.f};
    #pragma unroll
    for (int i = 0; i < 8; i++) {
        int k = i * 32 + lane;
        float v = fc[(size_t)n * 256 + k];
        acc[0] += v * Wb[k * 2 + 0];
        acc[1] += v * Wb[k * 2 + 1];
        #pragma unroll
        for (int j = 0; j < 5; j++) acc[2 + j] += v * Ws[k * 5 + j];
    }
    #pragma unroll
    for (int off = 16; off > 0; off >>= 1) {
        #pragma unroll
        for (int j = 0; j < 7; j++) acc[j] += __shfl_xor_sync(0xffffffffu, acc[j], off);
    }
    if (lane == 0) {
        out[(size_t)n * 2 + 0] = acc[0] + bb[0];
        out[(size_t)n * 2 + 1] = acc[1] + bb[1];
        float* sev = out + (size_t)N_NODES * 2 + (size_t)n * 5;
        #pragma unroll
        for (int j = 0; j < 5; j++) sev[j] = acc[2 + j] + bs[j];
    }
}

// ---------------- launch ------------------------------------------------------
static inline void cvt(const float* in, __half* out, int n, cudaStream_t st = 0) {
    cvt_fp16_kernel<<<(n / 8 + 255) / 256, 256, 0, st>>>(in, out, n);
}
static inline void cvtT(const float* W, __half* out, int K, int N, cudaStream_t st = 0) {
    dim3 grid(N / 32, K / 32);
    cvt_fp16_transpose_kernel<<<grid, dim3(32, 8), 0, st>>>(W, out, K, N);
}

extern "C" void kernel_launch(void* const* d_in, const int* in_sizes, int n_in,
                              void* d_out, int out_size)
{
    const float* x        = (const float*)d_in[0];
    const int*   ei       = (const int*)d_in[1];
    const float* W1       = (const float*)d_in[2];
    const float* att_src1 = (const float*)d_in[3];
    const float* att_dst1 = (const float*)d_in[4];
    const float* Wres1    = (const float*)d_in[5];
    const float* b1       = (const float*)d_in[6];
    const float* W2       = (const float*)d_in[7];
    const float* att_src2 = (const float*)d_in[8];
    const float* att_dst2 = (const float*)d_in[9];
    const float* Wres2    = (const float*)d_in[10];
    const float* b2       = (const float*)d_in[11];
    const float* Wfc      = (const float*)d_in[12];
    const float* bfc      = (const float*)d_in[13];
    const float* Wb       = (const float*)d_in[14];
    const float* bb       = (const float*)d_in[15];
    const float* Ws       = (const float*)d_in[16];
    const float* bs       = (const float*)d_in[17];
    float* out = (float*)d_out;

    const int* src = ei;
    const int* dst = ei + N_EDGES;

    float *h2, *fc2, *asrc, *adst;
    __half *xl16, *res16, *at, *wt, *fc1h;
    int *deg, *off, *cur, *esrc;
    cudaGetSymbolAddress((void**)&xl16,  g_xl16);
    cudaGetSymbolAddress((void**)&res16, g_res16);
    cudaGetSymbolAddress((void**)&h2,    g_h2);
    cudaGetSymbolAddress((void**)&fc1h,  g_fc1h);
    cudaGetSymbolAddress((void**)&fc2,   g_fc2);
    cudaGetSymbolAddress((void**)&at,    g_at);
    cudaGetSymbolAddress((void**)&wt,    g_wt);
    cudaGetSymbolAddress((void**)&asrc,  g_asrc);
    cudaGetSymbolAddress((void**)&adst,  g_adst);
    cudaGetSymbolAddress((void**)&deg,   g_deg);
    cudaGetSymbolAddress((void**)&off,   g_off);
    cudaGetSymbolAddress((void**)&cur,   g_cur);
    cudaGetSymbolAddress((void**)&esrc,  g_esrc);

    static bool init_done = false;
    static cudaStream_t s1;
    static cudaEvent_t ev0, evCsr, evGemm1, evW2, evGemm2, evWfc;
    if (!init_done) {
        cudaFuncSetAttribute(mma_gemm_kernel<0>,
                             cudaFuncAttributeMaxDynamicSharedMemorySize, GEMM_SMEM);
        cudaFuncSetAttribute(mma_gemm_kernel<1>,
                             cudaFuncAttributeMaxDynamicSharedMemorySize, GEMM_SMEM);
        cudaStreamCreateWithFlags(&s1, cudaStreamNonBlocking);
        cudaEventCreateWithFlags(&ev0,    cudaEventDisableTiming);
        cudaEventCreateWithFlags(&evCsr,  cudaEventDisableTiming);
        cudaEventCreateWithFlags(&evGemm1, cudaEventDisableTiming);
        cudaEventCreateWithFlags(&evW2,   cudaEventDisableTiming);
        cudaEventCreateWithFlags(&evGemm2, cudaEventDisableTiming);
        cudaEventCreateWithFlags(&evWfc,  cudaEventDisableTiming);
        init_done = true;
    }

    const int mRows = (N_NODES + GBM - 1) / GBM;
    const int attnBlocks = (N_NODES * 4 + 7) / 8;
    const int nodeBlocks = (N_NODES + 7) / 8;
    const int edgeBlocks = (N_EDGES + 255) / 256;

    // fork side stream from main
    cudaEventRecord(ev0, 0);
    cudaStreamWaitEvent(s1, ev0, 0);

    // ---- side stream: CSR build (independent of GEMM chain) ----
    zero_deg_kernel<<<(N_NODES + 255) / 256, 256, 0, s1>>>(deg);
    hist_kernel<<<edgeBlocks, 256, 0, s1>>>(dst, deg);
    scan_kernel<<<1, 256, 0, s1>>>(deg, off, cur);
    scatter_kernel<<<edgeBlocks, 256, 0, s1>>>(src, dst, cur, esrc);
    cudaEventRecord(evCsr, s1);

    // ---- main: operand prep + fused layer1 GEMM ----
    // GEMM1 reads A from 'at'; region A (residual) -> res16 fp16, region B -> xl16.
    cvt(x, at, N_NODES * 768);
    cvtT(Wres1, wt, 768, 1024);
    cvtT(W1, wt + (size_t)1024 * 768, 768, 1024);
    {
        dim3 grid(2048 / GBN, mRows);
        mma_gemm_kernel<0><<<grid, 256, GEMM_SMEM>>>(at, wt, b1, nullptr,
                                                     nullptr, res16, xl16,
                                                     N_NODES, 2048, 768, 1024);
    }
    cudaEventRecord(evGemm1, 0);

    // ---- side stream: layer2 weight conversions (after GEMM1 done with wt) ----
    cudaStreamWaitEvent(s1, evGemm1, 0);
    cvtT(Wres2, wt, 1024, 256, s1);
    cvtT(W2, wt + (size_t)256 * 1024, 1024, 1024, s1);
    cudaEventRecord(evW2, s1);

    // ---- main: layer 1 aggregation (in-place into res16) ----
    attn_scores_kernel<<<attnBlocks, 256>>>(xl16, att_src1, att_dst1, asrc, adst);
    cudaStreamWaitEvent(0, evCsr, 0);
    gat_aggregate1_kernel<<<attnBlocks, 256>>>(off, esrc, xl16, asrc, adst, res16);

    // ---- main: fused layer2 GEMM (A = res16) ----
    cudaStreamWaitEvent(0, evW2, 0);
    {
        dim3 grid(1280 / GBN, mRows);
        mma_gemm_kernel<0><<<grid, 256, GEMM_SMEM>>>(res16, wt, b2, nullptr,
                                                     h2, nullptr, xl16,
                                                     N_NODES, 1280, 1024, 256);
    }
    cudaEventRecord(evGemm2, 0);

    // ---- side stream: fc weight conversion ----
    cudaStreamWaitEvent(s1, evGemm2, 0);
    cvtT(Wfc, wt, 256, 256, s1);
    cudaEventRecord(evWfc, s1);

    // ---- main: layer 2 aggregation -> fp16 'at' ----
    attn_scores_kernel<<<attnBlocks, 256>>>(xl16, att_src2, att_dst2, asrc, adst);
    gat_aggregate2_kernel<<<nodeBlocks, 256>>>(off, esrc, xl16, asrc, adst, h2, at);

    // ---- main: shared FC twice (fc1 fp16, fc2 fp32) ----
    cudaStreamWaitEvent(0, evWfc, 0);
    {
        dim3 grid(256 / GBN, mRows);
        mma_gemm_kernel<1><<<grid, 256, GEMM_SMEM>>>(at, wt, nullptr, bfc,
                                                     nullptr, nullptr, fc1h,
                                                     N_NODES, 256, 256, 0);
        mma_gemm_kernel<0><<<grid, 256, GEMM_SMEM>>>(fc1h, wt, bfc, nullptr,
                                                     fc2, nullptr, nullptr,
                                                     N_NODES, 256, 256, 256);
    }

    // ---- heads ----
    heads_kernel<<<nodeBlocks, 256>>>(fc2, Wb, bb, Ws, bs, out);
}